// round 6
// baseline (speedup 1.0000x reference)
#include <cuda_runtime.h>
#include <cuda_fp16.h>
#include <cstdint>

#define NNODES  50000
#define NEDGES  640000
#define HID     128
#define NRBF    50
#define TILE    128
#define NT      512
#define CUTOFF_F 5.0f
#define NTILES_N ((NNODES + TILE - 1) / TILE)
#define GRID_P  152

#define NBINS   16384
#define TSTEP   (CUTOFF_F / (float)(NBINS - 1))
#define TINV    ((float)(NBINS - 1) / CUTOFF_F)

#define RBF_W   (CUTOFF_F / 49.0f)
#define RBF_IW  (49.0f / CUTOFF_F)

#define XTS 132

typedef unsigned long long ull;

__device__ float   g_agg[NNODES * HID];
__device__ float   g_table[NBINS * HID];
__device__ __half2 g_htab[NBINS * HID];     // {value, slope} fp16 per channel
__device__ int     g_cnt[NNODES];           // histogram
__device__ int     g_off[NNODES + 1];       // CSR offsets
__device__ int     g_woff[NNODES];          // scatter cursors
__device__ int2    g_rec[NEDGES];           // {col, t as float bits}
__device__ unsigned g_ctr_node;
__device__ int g_is64;

// ---------- packed f32x2 helpers ----------
__device__ __forceinline__ void fma2(ull &acc, ull a, ull b) {
    asm("fma.rn.f32x2 %0, %1, %2, %0;" : "+l"(acc) : "l"(a), "l"(b));
}
__device__ __forceinline__ ull bcast2(float x) {
    ull r; asm("mov.b64 %0, {%1, %1};" : "=l"(r) : "f"(x)); return r;
}
__device__ __forceinline__ ull pack2(float x, float y) {
    ull r; asm("mov.b64 %0, {%1, %2};" : "=l"(r) : "f"(x), "f"(y)); return r;
}
__device__ __forceinline__ float2 unpack2(ull v) {
    float2 f; asm("mov.b64 {%0, %1}, %2;" : "=f"(f.x), "=f"(f.y) : "l"(v)); return f;
}
__device__ __forceinline__ float silu_f(float x) {
    return x / (1.0f + __expf(-x));
}

// ---------- edge index load helper ----------
__device__ __forceinline__ void load_edge(const void* ei, int is64, int g, int &r, int &c) {
    if (is64) {
        r = (int)__ldg((const long long*)ei + g);
        c = (int)__ldg((const long long*)ei + NEDGES + g);
    } else {
        r = __ldg((const int*)ei + g);
        c = __ldg((const int*)ei + NEDGES + g);
    }
}
__device__ __forceinline__ float edge_dist(const float* pos, int r, int c) {
    float dx = pos[r*3+0] - pos[c*3+0];
    float dy = pos[r*3+1] - pos[c*3+1];
    float dz = pos[r*3+2] - pos[c*3+2];
    return sqrtf(dx*dx + dy*dy + dz*dz + 1e-8f);
}

// ---------- init: zero counters + dtype flag ----------
__global__ void init_kernel(const void* ei) {
    if (blockIdx.x == 0 && threadIdx.x == 0) {
        g_ctr_node = 0u;
        const unsigned* u = (const unsigned*)ei;
        unsigned acc = 0;
        #pragma unroll
        for (int i = 0; i < 64; i++) acc |= u[2*i + 1];
        g_is64 = (acc == 0);
    }
    for (int i = blockIdx.x * blockDim.x + threadIdx.x; i < NNODES; i += gridDim.x * blockDim.x)
        g_cnt[i] = 0;
}

// ---------- histogram of valid edges by row ----------
__global__ void hist_kernel(const float* __restrict__ pos, const void* __restrict__ ei) {
    const int is64 = g_is64;
    for (int g = blockIdx.x * blockDim.x + threadIdx.x; g < NEDGES; g += gridDim.x * blockDim.x) {
        int r, c; load_edge(ei, is64, g, r, c);
        float d = edge_dist(pos, r, c);
        if (d <= CUTOFF_F) atomicAdd(&g_cnt[r], 1);
    }
}

// ---------- single-CTA exclusive scan ----------
#define SCT 1024
__global__ void scan_kernel() {
    __shared__ int s[SCT];
    const int tid = threadIdx.x;
    const int P = (NNODES + SCT - 1) / SCT;
    const int t0 = tid * P;
    const int t1 = min(t0 + P, NNODES);

    int local = 0;
    for (int i = t0; i < t1; i++) local += g_cnt[i];
    s[tid] = local;
    __syncthreads();
    for (int ofs = 1; ofs < SCT; ofs <<= 1) {
        int v = (tid >= ofs) ? s[tid - ofs] : 0;
        __syncthreads();
        s[tid] += v;
        __syncthreads();
    }
    int run = s[tid] - local;   // exclusive
    for (int i = t0; i < t1; i++) {
        int cn = g_cnt[i];
        g_off[i] = run;
        g_woff[i] = run;
        run += cn;
    }
    if (tid == SCT - 1) g_off[NNODES] = s[SCT - 1];
}

// ---------- scatter edge records into CSR ----------
__global__ void scatter_kernel(const float* __restrict__ pos, const void* __restrict__ ei) {
    const int is64 = g_is64;
    for (int g = blockIdx.x * blockDim.x + threadIdx.x; g < NEDGES; g += gridDim.x * blockDim.x) {
        int r, c; load_edge(ei, is64, g, r, c);
        float d = edge_dist(pos, r, c);
        if (d > CUTOFF_F) continue;
        float t = d * TINV;
        if (t > (float)(NBINS - 1)) t = (float)(NBINS - 1);
        int slot = atomicAdd(&g_woff[r], 1);
        g_rec[slot] = make_int2(c, __float_as_int(t));
    }
}

// ---------- table build kernel ----------
#define TBL_SMEM_FLOATS (NRBF*HID + HID*HID + TILE*NRBF + TILE*HID + TILE)
#define TBL_SMEM_BYTES  (TBL_SMEM_FLOATS * 4)

__global__ __launch_bounds__(NT, 1)
void table_kernel(const float* __restrict__ fw1, const float* __restrict__ fb1,
                  const float* __restrict__ fw2, const float* __restrict__ fb2)
{
    extern __shared__ float sm[];
    float* fw1_s  = sm;
    float* fw2_s  = fw1_s + NRBF * HID;
    float* rbf_s  = fw2_s + HID * HID;
    float* s1_s   = rbf_s + TILE * NRBF;
    float* cut_s  = s1_s + TILE * HID;

    const int tid = threadIdx.x;
    const int rbase = blockIdx.x * TILE;

    {
        const float4* w1 = (const float4*)fw1; float4* d1 = (float4*)fw1_s;
        for (int i = tid; i < NRBF*HID/4; i += NT) d1[i] = w1[i];
        const float4* w2 = (const float4*)fw2; float4* d2 = (float4*)fw2_s;
        for (int i = tid; i < HID*HID/4; i += NT) d2[i] = w2[i];
    }
    if (tid < TILE) {
        float d = (float)(rbase + tid) * TSTEP;
        cut_s[tid] = 0.5f * (__cosf(d * (3.14159265358979323846f / CUTOFF_F)) + 1.0f);
    }
    for (int idx = tid; idx < TILE * NRBF; idx += NT) {
        int e = idx / NRBF;
        int k = idx - e * NRBF;
        float d = (float)(rbase + e) * TSTEP;
        float t = (d - (float)k * RBF_W) * RBF_IW;
        rbf_s[idx] = __expf(-0.5f * t * t);
    }
    __syncthreads();

    const int eg0 = (tid >> 4) * 4;
    const int c0  = (tid & 15) * 8;

    ull acc[4][4];
    {
        float4 ba = *(const float4*)(fb1 + c0);
        float4 bb = *(const float4*)(fb1 + c0 + 4);
        ull i0 = pack2(ba.x, ba.y), i1 = pack2(ba.z, ba.w);
        ull i2 = pack2(bb.x, bb.y), i3 = pack2(bb.z, bb.w);
        #pragma unroll
        for (int i = 0; i < 4; i++) { acc[i][0]=i0; acc[i][1]=i1; acc[i][2]=i2; acc[i][3]=i3; }
    }
    {
        const float* rb = rbf_s + eg0 * NRBF;
        #pragma unroll 2
        for (int k = 0; k < NRBF; k++) {
            ull a0 = bcast2(rb[k]);
            ull a1 = bcast2(rb[k +   NRBF]);
            ull a2 = bcast2(rb[k + 2*NRBF]);
            ull a3 = bcast2(rb[k + 3*NRBF]);
            const ulonglong2* wp = (const ulonglong2*)(fw1_s + k*HID + c0);
            ulonglong2 w01 = wp[0], w23 = wp[1];
            fma2(acc[0][0],a0,w01.x); fma2(acc[0][1],a0,w01.y); fma2(acc[0][2],a0,w23.x); fma2(acc[0][3],a0,w23.y);
            fma2(acc[1][0],a1,w01.x); fma2(acc[1][1],a1,w01.y); fma2(acc[1][2],a1,w23.x); fma2(acc[1][3],a1,w23.y);
            fma2(acc[2][0],a2,w01.x); fma2(acc[2][1],a2,w01.y); fma2(acc[2][2],a2,w23.x); fma2(acc[2][3],a2,w23.y);
            fma2(acc[3][0],a3,w01.x); fma2(acc[3][1],a3,w01.y); fma2(acc[3][2],a3,w23.x); fma2(acc[3][3],a3,w23.y);
        }
    }
    #pragma unroll
    for (int i = 0; i < 4; i++) {
        float4 o0, o1; float2 v;
        v = unpack2(acc[i][0]); o0.x = silu_f(v.x); o0.y = silu_f(v.y);
        v = unpack2(acc[i][1]); o0.z = silu_f(v.x); o0.w = silu_f(v.y);
        v = unpack2(acc[i][2]); o1.x = silu_f(v.x); o1.y = silu_f(v.y);
        v = unpack2(acc[i][3]); o1.z = silu_f(v.x); o1.w = silu_f(v.y);
        *(float4*)(s1_s + (eg0+i)*HID + c0)     = o0;
        *(float4*)(s1_s + (eg0+i)*HID + c0 + 4) = o1;
    }
    __syncthreads();

    {
        float4 ba = *(const float4*)(fb2 + c0);
        float4 bb = *(const float4*)(fb2 + c0 + 4);
        ull i0 = pack2(ba.x, ba.y), i1 = pack2(ba.z, ba.w);
        ull i2 = pack2(bb.x, bb.y), i3 = pack2(bb.z, bb.w);
        #pragma unroll
        for (int i = 0; i < 4; i++) { acc[i][0]=i0; acc[i][1]=i1; acc[i][2]=i2; acc[i][3]=i3; }
    }
    {
        const float* sb = s1_s + eg0 * HID;
        #pragma unroll 2
        for (int k = 0; k < HID; k++) {
            ull a0 = bcast2(sb[k]);
            ull a1 = bcast2(sb[k +   HID]);
            ull a2 = bcast2(sb[k + 2*HID]);
            ull a3 = bcast2(sb[k + 3*HID]);
            const ulonglong2* wp = (const ulonglong2*)(fw2_s + k*HID + c0);
            ulonglong2 w01 = wp[0], w23 = wp[1];
            fma2(acc[0][0],a0,w01.x); fma2(acc[0][1],a0,w01.y); fma2(acc[0][2],a0,w23.x); fma2(acc[0][3],a0,w23.y);
            fma2(acc[1][0],a1,w01.x); fma2(acc[1][1],a1,w01.y); fma2(acc[1][2],a1,w23.x); fma2(acc[1][3],a1,w23.y);
            fma2(acc[2][0],a2,w01.x); fma2(acc[2][1],a2,w01.y); fma2(acc[2][2],a2,w23.x); fma2(acc[2][3],a2,w23.y);
            fma2(acc[3][0],a3,w01.x); fma2(acc[3][1],a3,w01.y); fma2(acc[3][2],a3,w23.x); fma2(acc[3][3],a3,w23.y);
        }
    }
    #pragma unroll
    for (int i = 0; i < 4; i++) {
        int r = rbase + eg0 + i;
        float ct = cut_s[eg0 + i];
        float2 v0 = unpack2(acc[i][0]);
        float2 v1 = unpack2(acc[i][1]);
        float2 v2 = unpack2(acc[i][2]);
        float2 v3 = unpack2(acc[i][3]);
        float4 o0 = make_float4(v0.x*ct, v0.y*ct, v1.x*ct, v1.y*ct);
        float4 o1 = make_float4(v2.x*ct, v2.y*ct, v3.x*ct, v3.y*ct);
        *(float4*)(g_table + r*HID + c0)     = o0;
        *(float4*)(g_table + r*HID + c0 + 4) = o1;
    }
}

// ---------- interleaved fp16 {value, slope} table ----------
__global__ void htab_kernel() {
    int idx = blockIdx.x * blockDim.x + threadIdx.x;
    const int n = NBINS * HID;
    if (idx >= n) return;
    float v = g_table[idx];
    float s = (idx + HID < n) ? (g_table[idx + HID] - v) : 0.f;
    g_htab[idx] = __floats2half2_rn(v, s);
}

// ---------- CSR gather: one warp per node, no atomics ----------
#define GNT 256
#define GGRID 1184

__global__ __launch_bounds__(GNT)
void gather_kernel(const float* __restrict__ hin)
{
    const int lane = threadIdx.x & 31;
    const int c0 = lane * 4;
    int n = (blockIdx.x * GNT + threadIdx.x) >> 5;
    const int nstride = (GGRID * GNT) >> 5;

    for (; n < NNODES; n += nstride) {
        const int start = __ldg(&g_off[n]);
        const int end   = __ldg(&g_off[n + 1]);
        float4 acc = make_float4(0.f, 0.f, 0.f, 0.f);

        #pragma unroll 2
        for (int e = start; e < end; e++) {
            int2 rec = __ldg(&g_rec[e]);            // broadcast across warp
            float t = __int_as_float(rec.y);
            int i0 = (int)t;
            float fr = t - (float)i0;

            uint4 q = *(const uint4*)(g_htab + i0*HID + c0);   // 4 ch {v,s}
            float4 hv = __ldg((const float4*)(hin + rec.x*HID + c0));

            float2 t0 = __half22float2(*(__half2*)&q.x);
            float2 t1 = __half22float2(*(__half2*)&q.y);
            float2 t2 = __half22float2(*(__half2*)&q.z);
            float2 t3 = __half22float2(*(__half2*)&q.w);

            acc.x = fmaf(hv.x, fmaf(fr, t0.y, t0.x), acc.x);
            acc.y = fmaf(hv.y, fmaf(fr, t1.y, t1.x), acc.y);
            acc.z = fmaf(hv.z, fmaf(fr, t2.y, t2.x), acc.z);
            acc.w = fmaf(hv.w, fmaf(fr, t3.y, t3.x), acc.w);
        }
        *(float4*)(g_agg + n*HID + c0) = acc;
    }
}

// ---------- persistent node kernel (unchanged from R5) ----------
#define NODE_SMEM_BYTES ((2 * HID * HID + HID * XTS) * 4)

__global__ __launch_bounds__(NT, 1)
void node_kernel(const float* __restrict__ hin, float* __restrict__ out,
                 const float* __restrict__ iw1, const float* __restrict__ ib1,
                 const float* __restrict__ iw2, const float* __restrict__ ib2)
{
    extern __shared__ float sm[];
    float* iw1_s = sm;
    float* iw2_s = iw1_s + HID * HID;
    float* xT    = iw2_s + HID * HID;
    __shared__ int s_tile;

    const int tid  = threadIdx.x;
    const int wid  = tid >> 5;
    const int lane = tid & 31;
    const int c0   = wid * 8;
    const int e0   = lane * 4;

    {
        const float4* w1 = (const float4*)iw1; float4* d1 = (float4*)iw1_s;
        for (int i = tid; i < HID*HID/4; i += NT) d1[i] = w1[i];
        const float4* w2 = (const float4*)iw2; float4* d2 = (float4*)iw2_s;
        for (int i = tid; i < HID*HID/4; i += NT) d2[i] = w2[i];
    }

    ull b1p[4], b2p[4];
    {
        float4 ba = *(const float4*)(ib1 + c0);
        float4 bb = *(const float4*)(ib1 + c0 + 4);
        b1p[0] = pack2(ba.x, ba.y); b1p[1] = pack2(ba.z, ba.w);
        b1p[2] = pack2(bb.x, bb.y); b1p[3] = pack2(bb.z, bb.w);
        ba = *(const float4*)(ib2 + c0);
        bb = *(const float4*)(ib2 + c0 + 4);
        b2p[0] = pack2(ba.x, ba.y); b2p[1] = pack2(ba.z, ba.w);
        b2p[2] = pack2(bb.x, bb.y); b2p[3] = pack2(bb.z, bb.w);
    }

    while (true) {
        __syncthreads();
        if (tid == 0) s_tile = (int)atomicAdd(&g_ctr_node, 1u);
        __syncthreads();
        const int tile = s_tile;
        if (tile >= NTILES_N) break;
        const int nbase = tile * TILE;

        for (int idx = tid; idx < TILE * (HID/4); idx += NT) {
            int n  = idx & 127;
            int c4 = idx >> 7;
            float4 v = make_float4(0.f,0.f,0.f,0.f);
            int gn = nbase + n;
            if (gn < NNODES) v = __ldg((const float4*)(g_agg + gn*HID + c4*4));
            xT[(c4*4+0)*XTS + n] = v.x;
            xT[(c4*4+1)*XTS + n] = v.y;
            xT[(c4*4+2)*XTS + n] = v.z;
            xT[(c4*4+3)*XTS + n] = v.w;
        }
        __syncthreads();

        ull acc[16];
        #pragma unroll
        for (int e = 0; e < 4; e++) {
            acc[e*4+0]=b1p[0]; acc[e*4+1]=b1p[1]; acc[e*4+2]=b1p[2]; acc[e*4+3]=b1p[3];
        }
        for (int k = 0; k < HID; k += 4) {
            float4 av[4];
            ulonglong2 w01[4], w23[4];
            #pragma unroll
            for (int u = 0; u < 4; u++) {
                av[u] = *(const float4*)(xT + (k+u)*XTS + e0);
                const ulonglong2* wp = (const ulonglong2*)(iw1_s + (k+u)*HID + c0);
                w01[u] = wp[0]; w23[u] = wp[1];
            }
            #pragma unroll
            for (int u = 0; u < 4; u++) {
                ull a0 = bcast2(av[u].x), a1 = bcast2(av[u].y), a2 = bcast2(av[u].z), a3 = bcast2(av[u].w);
                fma2(acc[0],a0,w01[u].x);  fma2(acc[1],a0,w01[u].y);  fma2(acc[2],a0,w23[u].x);  fma2(acc[3],a0,w23[u].y);
                fma2(acc[4],a1,w01[u].x);  fma2(acc[5],a1,w01[u].y);  fma2(acc[6],a1,w23[u].x);  fma2(acc[7],a1,w23[u].y);
                fma2(acc[8],a2,w01[u].x);  fma2(acc[9],a2,w01[u].y);  fma2(acc[10],a2,w23[u].x); fma2(acc[11],a2,w23[u].y);
                fma2(acc[12],a3,w01[u].x); fma2(acc[13],a3,w01[u].y); fma2(acc[14],a3,w23[u].x); fma2(acc[15],a3,w23[u].y);
            }
        }
        __syncthreads();

        #pragma unroll
        for (int cp = 0; cp < 4; cp++) {
            float2 v0 = unpack2(acc[0*4+cp]);
            float2 v1 = unpack2(acc[1*4+cp]);
            float2 v2 = unpack2(acc[2*4+cp]);
            float2 v3 = unpack2(acc[3*4+cp]);
            float4 oA = make_float4(silu_f(v0.x), silu_f(v1.x), silu_f(v2.x), silu_f(v3.x));
            float4 oB = make_float4(silu_f(v0.y), silu_f(v1.y), silu_f(v2.y), silu_f(v3.y));
            *(float4*)(xT + (c0 + 2*cp    )*XTS + e0) = oA;
            *(float4*)(xT + (c0 + 2*cp + 1)*XTS + e0) = oB;
        }
        __syncthreads();

        #pragma unroll
        for (int e = 0; e < 4; e++) {
            acc[e*4+0]=b2p[0]; acc[e*4+1]=b2p[1]; acc[e*4+2]=b2p[2]; acc[e*4+3]=b2p[3];
        }
        for (int k = 0; k < HID; k += 4) {
            float4 av[4];
            ulonglong2 w01[4], w23[4];
            #pragma unroll
            for (int u = 0; u < 4; u++) {
                av[u] = *(const float4*)(xT + (k+u)*XTS + e0);
                const ulonglong2* wp = (const ulonglong2*)(iw2_s + (k+u)*HID + c0);
                w01[u] = wp[0]; w23[u] = wp[1];
            }
            #pragma unroll
            for (int u = 0; u < 4; u++) {
                ull a0 = bcast2(av[u].x), a1 = bcast2(av[u].y), a2 = bcast2(av[u].z), a3 = bcast2(av[u].w);
                fma2(acc[0],a0,w01[u].x);  fma2(acc[1],a0,w01[u].y);  fma2(acc[2],a0,w23[u].x);  fma2(acc[3],a0,w23[u].y);
                fma2(acc[4],a1,w01[u].x);  fma2(acc[5],a1,w01[u].y);  fma2(acc[6],a1,w23[u].x);  fma2(acc[7],a1,w23[u].y);
                fma2(acc[8],a2,w01[u].x);  fma2(acc[9],a2,w01[u].y);  fma2(acc[10],a2,w23[u].x); fma2(acc[11],a2,w23[u].y);
                fma2(acc[12],a3,w01[u].x); fma2(acc[13],a3,w01[u].y); fma2(acc[14],a3,w23[u].x); fma2(acc[15],a3,w23[u].y);
            }
        }

        #pragma unroll
        for (int e = 0; e < 4; e++) {
            int n = nbase + e0 + e;
            if (n >= NNODES) continue;
            float4 h0 = __ldg((const float4*)(hin + n*HID + c0));
            float4 h1 = __ldg((const float4*)(hin + n*HID + c0 + 4));
            float2 v0 = unpack2(acc[e*4+0]);
            float2 v1 = unpack2(acc[e*4+1]);
            float2 v2 = unpack2(acc[e*4+2]);
            float2 v3 = unpack2(acc[e*4+3]);
            float4 o0 = make_float4(h0.x + v0.x, h0.y + v0.y, h0.z + v1.x, h0.w + v1.y);
            float4 o1 = make_float4(h1.x + v2.x, h1.y + v2.y, h1.z + v3.x, h1.w + v3.y);
            *(float4*)(out + n*HID + c0)     = o0;
            *(float4*)(out + n*HID + c0 + 4) = o1;
        }
    }
}

extern "C" void kernel_launch(void* const* d_in, const int* in_sizes, int n_in,
                              void* d_out, int out_size)
{
    const float* h    = (const float*)d_in[0];
    const float* pos  = (const float*)d_in[1];
    const void*  ei   = d_in[2];
    const float* fw1  = (const float*)d_in[3];
    const float* fb1  = (const float*)d_in[4];
    const float* fw2  = (const float*)d_in[5];
    const float* fb2  = (const float*)d_in[6];
    const float* iw1  = (const float*)d_in[7];
    const float* ib1  = (const float*)d_in[8];
    const float* iw2  = (const float*)d_in[9];
    const float* ib2  = (const float*)d_in[10];
    float* out = (float*)d_out;

    cudaFuncSetAttribute(table_kernel, cudaFuncAttributeMaxDynamicSharedMemorySize, TBL_SMEM_BYTES);
    cudaFuncSetAttribute(node_kernel, cudaFuncAttributeMaxDynamicSharedMemorySize, NODE_SMEM_BYTES);

    init_kernel<<<128, 512>>>(ei);
    hist_kernel<<<GGRID, GNT>>>(pos, ei);
    scan_kernel<<<1, SCT>>>();
    scatter_kernel<<<GGRID, GNT>>>(pos, ei);
    table_kernel<<<NBINS / TILE, NT, TBL_SMEM_BYTES>>>(fw1, fb1, fw2, fb2);
    htab_kernel<<<(NBINS * HID + 255) / 256, 256>>>();
    gather_kernel<<<GGRID, GNT>>>(h);
    node_kernel<<<GRID_P, NT, NODE_SMEM_BYTES>>>(h, out, iw1, ib1, iw2, ib2);
}

// round 8
// speedup vs baseline: 1.1471x; 1.1471x over previous
#include <cuda_runtime.h>
#include <cuda_fp16.h>
#include <cstdint>

#define NNODES  50000
#define NEDGES  640000
#define HID     128
#define NRBF    50
#define TILE    128
#define NT      512
#define CUTOFF_F 5.0f
#define NTILES_N ((NNODES + TILE - 1) / TILE)
#define GRID_P  152

#define NBINS   4096
#define TSTEP   (CUTOFF_F / (float)(NBINS - 1))
#define TINV    ((float)(NBINS - 1) / CUTOFF_F)

#define RBF_W   (CUTOFF_F / 49.0f)
#define RBF_IW  (49.0f / CUTOFF_F)

#define XTS 132

typedef unsigned long long ull;

__device__ float   g_agg[NNODES * HID];
__device__ float   g_table[NBINS * HID];
__device__ __half2 g_htab[NBINS * HID];     // {value, slope} fp16 per channel
__device__ unsigned g_ctr_node;
__device__ int g_is64;

// ---------- packed f32x2 helpers ----------
__device__ __forceinline__ void fma2(ull &acc, ull a, ull b) {
    asm("fma.rn.f32x2 %0, %1, %2, %0;" : "+l"(acc) : "l"(a), "l"(b));
}
__device__ __forceinline__ ull bcast2(float x) {
    ull r; asm("mov.b64 %0, {%1, %1};" : "=l"(r) : "f"(x)); return r;
}
__device__ __forceinline__ ull pack2(float x, float y) {
    ull r; asm("mov.b64 %0, {%1, %2};" : "=l"(r) : "f"(x), "f"(y)); return r;
}
__device__ __forceinline__ float2 unpack2(ull v) {
    float2 f; asm("mov.b64 {%0, %1}, %2;" : "=f"(f.x), "=f"(f.y) : "l"(v)); return f;
}
__device__ __forceinline__ void red4(float* p, float a, float b, float c, float d) {
    asm volatile("red.global.add.v4.f32 [%0], {%1,%2,%3,%4};"
                 :: "l"(p), "f"(a), "f"(b), "f"(c), "f"(d) : "memory");
}
__device__ __forceinline__ float silu_f(float x) {
    return x / (1.0f + __expf(-x));
}

// ---------- zero scratch + counters + dtype flag ----------
__global__ void zero_kernel(const void* ei) {
    if (blockIdx.x == 0 && threadIdx.x == 0) {
        g_ctr_node = 0u;
        const unsigned* u = (const unsigned*)ei;
        unsigned acc = 0;
        #pragma unroll
        for (int i = 0; i < 64; i++) acc |= u[2*i + 1];
        g_is64 = (acc == 0);
    }
    float4* p = (float4*)g_agg;
    const int n = NNODES * HID / 4;
    for (int i = blockIdx.x * blockDim.x + threadIdx.x; i < n; i += gridDim.x * blockDim.x)
        p[i] = make_float4(0.f, 0.f, 0.f, 0.f);
}

// ---------- table build kernel ----------
#define TBL_SMEM_FLOATS (NRBF*HID + HID*HID + TILE*NRBF + TILE*HID + TILE)
#define TBL_SMEM_BYTES  (TBL_SMEM_FLOATS * 4)

__global__ __launch_bounds__(NT, 1)
void table_kernel(const float* __restrict__ fw1, const float* __restrict__ fb1,
                  const float* __restrict__ fw2, const float* __restrict__ fb2)
{
    extern __shared__ float sm[];
    float* fw1_s  = sm;
    float* fw2_s  = fw1_s + NRBF * HID;
    float* rbf_s  = fw2_s + HID * HID;
    float* s1_s   = rbf_s + TILE * NRBF;
    float* cut_s  = s1_s + TILE * HID;

    const int tid = threadIdx.x;
    const int rbase = blockIdx.x * TILE;

    {
        const float4* w1 = (const float4*)fw1; float4* d1 = (float4*)fw1_s;
        for (int i = tid; i < NRBF*HID/4; i += NT) d1[i] = w1[i];
        const float4* w2 = (const float4*)fw2; float4* d2 = (float4*)fw2_s;
        for (int i = tid; i < HID*HID/4; i += NT) d2[i] = w2[i];
    }
    if (tid < TILE) {
        float d = (float)(rbase + tid) * TSTEP;
        cut_s[tid] = 0.5f * (__cosf(d * (3.14159265358979323846f / CUTOFF_F)) + 1.0f);
    }
    for (int idx = tid; idx < TILE * NRBF; idx += NT) {
        int e = idx / NRBF;
        int k = idx - e * NRBF;
        float d = (float)(rbase + e) * TSTEP;
        float t = (d - (float)k * RBF_W) * RBF_IW;
        rbf_s[idx] = __expf(-0.5f * t * t);
    }
    __syncthreads();

    const int eg0 = (tid >> 4) * 4;
    const int c0  = (tid & 15) * 8;

    ull acc[4][4];
    {
        float4 ba = *(const float4*)(fb1 + c0);
        float4 bb = *(const float4*)(fb1 + c0 + 4);
        ull i0 = pack2(ba.x, ba.y), i1 = pack2(ba.z, ba.w);
        ull i2 = pack2(bb.x, bb.y), i3 = pack2(bb.z, bb.w);
        #pragma unroll
        for (int i = 0; i < 4; i++) { acc[i][0]=i0; acc[i][1]=i1; acc[i][2]=i2; acc[i][3]=i3; }
    }
    {
        const float* rb = rbf_s + eg0 * NRBF;
        #pragma unroll 2
        for (int k = 0; k < NRBF; k++) {
            ull a0 = bcast2(rb[k]);
            ull a1 = bcast2(rb[k +   NRBF]);
            ull a2 = bcast2(rb[k + 2*NRBF]);
            ull a3 = bcast2(rb[k + 3*NRBF]);
            const ulonglong2* wp = (const ulonglong2*)(fw1_s + k*HID + c0);
            ulonglong2 w01 = wp[0], w23 = wp[1];
            fma2(acc[0][0],a0,w01.x); fma2(acc[0][1],a0,w01.y); fma2(acc[0][2],a0,w23.x); fma2(acc[0][3],a0,w23.y);
            fma2(acc[1][0],a1,w01.x); fma2(acc[1][1],a1,w01.y); fma2(acc[1][2],a1,w23.x); fma2(acc[1][3],a1,w23.y);
            fma2(acc[2][0],a2,w01.x); fma2(acc[2][1],a2,w01.y); fma2(acc[2][2],a2,w23.x); fma2(acc[2][3],a2,w23.y);
            fma2(acc[3][0],a3,w01.x); fma2(acc[3][1],a3,w01.y); fma2(acc[3][2],a3,w23.x); fma2(acc[3][3],a3,w23.y);
        }
    }
    #pragma unroll
    for (int i = 0; i < 4; i++) {
        float4 o0, o1; float2 v;
        v = unpack2(acc[i][0]); o0.x = silu_f(v.x); o0.y = silu_f(v.y);
        v = unpack2(acc[i][1]); o0.z = silu_f(v.x); o0.w = silu_f(v.y);
        v = unpack2(acc[i][2]); o1.x = silu_f(v.x); o1.y = silu_f(v.y);
        v = unpack2(acc[i][3]); o1.z = silu_f(v.x); o1.w = silu_f(v.y);
        *(float4*)(s1_s + (eg0+i)*HID + c0)     = o0;
        *(float4*)(s1_s + (eg0+i)*HID + c0 + 4) = o1;
    }
    __syncthreads();

    {
        float4 ba = *(const float4*)(fb2 + c0);
        float4 bb = *(const float4*)(fb2 + c0 + 4);
        ull i0 = pack2(ba.x, ba.y), i1 = pack2(ba.z, ba.w);
        ull i2 = pack2(bb.x, bb.y), i3 = pack2(bb.z, bb.w);
        #pragma unroll
        for (int i = 0; i < 4; i++) { acc[i][0]=i0; acc[i][1]=i1; acc[i][2]=i2; acc[i][3]=i3; }
    }
    {
        const float* sb = s1_s + eg0 * HID;
        #pragma unroll 2
        for (int k = 0; k < HID; k++) {
            ull a0 = bcast2(sb[k]);
            ull a1 = bcast2(sb[k +   HID]);
            ull a2 = bcast2(sb[k + 2*HID]);
            ull a3 = bcast2(sb[k + 3*HID]);
            const ulonglong2* wp = (const ulonglong2*)(fw2_s + k*HID + c0);
            ulonglong2 w01 = wp[0], w23 = wp[1];
            fma2(acc[0][0],a0,w01.x); fma2(acc[0][1],a0,w01.y); fma2(acc[0][2],a0,w23.x); fma2(acc[0][3],a0,w23.y);
            fma2(acc[1][0],a1,w01.x); fma2(acc[1][1],a1,w01.y); fma2(acc[1][2],a1,w23.x); fma2(acc[1][3],a1,w23.y);
            fma2(acc[2][0],a2,w01.x); fma2(acc[2][1],a2,w01.y); fma2(acc[2][2],a2,w23.x); fma2(acc[2][3],a2,w23.y);
            fma2(acc[3][0],a3,w01.x); fma2(acc[3][1],a3,w01.y); fma2(acc[3][2],a3,w23.x); fma2(acc[3][3],a3,w23.y);
        }
    }
    #pragma unroll
    for (int i = 0; i < 4; i++) {
        int r = rbase + eg0 + i;
        float ct = cut_s[eg0 + i];
        float2 v0 = unpack2(acc[i][0]);
        float2 v1 = unpack2(acc[i][1]);
        float2 v2 = unpack2(acc[i][2]);
        float2 v3 = unpack2(acc[i][3]);
        float4 o0 = make_float4(v0.x*ct, v0.y*ct, v1.x*ct, v1.y*ct);
        float4 o1 = make_float4(v2.x*ct, v2.y*ct, v3.x*ct, v3.y*ct);
        *(float4*)(g_table + r*HID + c0)     = o0;
        *(float4*)(g_table + r*HID + c0 + 4) = o1;
    }
}

// ---------- interleaved fp16 {value, slope} table ----------
__global__ void htab_kernel() {
    int idx = blockIdx.x * blockDim.x + threadIdx.x;
    const int n = NBINS * HID;
    if (idx >= n) return;
    float v = g_table[idx];
    float s = (idx + HID < n) ? (g_table[idx + HID] - v) : 0.f;
    g_htab[idx] = __floats2half2_rn(v, s);
}

// ---------- edge gather/lerp/scatter (atomic v4) ----------
#define GNT 256
#define GGRID 1184

__global__ __launch_bounds__(GNT)
void gather_kernel(const float* __restrict__ hin, const float* __restrict__ pos,
                   const void* __restrict__ ei)
{
    const int is64 = g_is64;
    const int lane16 = threadIdx.x & 15;
    const int c0 = lane16 * 8;
    const int gpb = GNT / 16;
    int g = blockIdx.x * gpb + (threadIdx.x >> 4);
    const int gstride = GGRID * gpb;

    for (; g < NEDGES; g += gstride) {
        int r, c;
        if (is64) {
            r = (int)__ldg((const long long*)ei + g);
            c = (int)__ldg((const long long*)ei + NEDGES + g);
        } else {
            r = __ldg((const int*)ei + g);
            c = __ldg((const int*)ei + NEDGES + g);
        }
        float dx = pos[r*3+0] - pos[c*3+0];
        float dy = pos[r*3+1] - pos[c*3+1];
        float dz = pos[r*3+2] - pos[c*3+2];
        float d  = sqrtf(dx*dx + dy*dy + dz*dz + 1e-8f);
        if (d > CUTOFF_F) continue;

        float t = d * TINV;
        int i0 = (int)t;
        if (i0 > NBINS - 1) i0 = NBINS - 1;
        float fr = t - (float)i0;

        const uint4* Tp = (const uint4*)(g_htab + i0*HID + c0);
        uint4 q0 = Tp[0];
        uint4 q1 = Tp[1];
        float4 h0 = *(const float4*)(hin + c*HID + c0);
        float4 h1 = *(const float4*)(hin + c*HID + c0 + 4);

        float2 t0 = __half22float2(*(__half2*)&q0.x);
        float2 t1 = __half22float2(*(__half2*)&q0.y);
        float2 t2 = __half22float2(*(__half2*)&q0.z);
        float2 t3 = __half22float2(*(__half2*)&q0.w);
        float2 t4 = __half22float2(*(__half2*)&q1.x);
        float2 t5 = __half22float2(*(__half2*)&q1.y);
        float2 t6 = __half22float2(*(__half2*)&q1.z);
        float2 t7 = __half22float2(*(__half2*)&q1.w);

        float w0 = fmaf(fr, t0.y, t0.x);
        float w1 = fmaf(fr, t1.y, t1.x);
        float w2 = fmaf(fr, t2.y, t2.x);
        float w3 = fmaf(fr, t3.y, t3.x);
        float w4 = fmaf(fr, t4.y, t4.x);
        float w5 = fmaf(fr, t5.y, t5.x);
        float w6 = fmaf(fr, t6.y, t6.x);
        float w7 = fmaf(fr, t7.y, t7.x);

        float* dst = g_agg + r*HID + c0;
        red4(dst,     h0.x*w0, h0.y*w1, h0.z*w2, h0.w*w3);
        red4(dst + 4, h1.x*w4, h1.y*w5, h1.z*w6, h1.w*w7);
    }
}

// ---------- persistent node kernel (R5 warp-owns-columns) ----------
#define NODE_SMEM_BYTES ((2 * HID * HID + HID * XTS) * 4)

__global__ __launch_bounds__(NT, 1)
void node_kernel(const float* __restrict__ hin, float* __restrict__ out,
                 const float* __restrict__ iw1, const float* __restrict__ ib1,
                 const float* __restrict__ iw2, const float* __restrict__ ib2)
{
    extern __shared__ float sm[];
    float* iw1_s = sm;
    float* iw2_s = iw1_s + HID * HID;
    float* xT    = iw2_s + HID * HID;
    __shared__ int s_tile;

    const int tid  = threadIdx.x;
    const int wid  = tid >> 5;
    const int lane = tid & 31;
    const int c0   = wid * 8;
    const int e0   = lane * 4;

    {
        const float4* w1 = (const float4*)iw1; float4* d1 = (float4*)iw1_s;
        for (int i = tid; i < HID*HID/4; i += NT) d1[i] = w1[i];
        const float4* w2 = (const float4*)iw2; float4* d2 = (float4*)iw2_s;
        for (int i = tid; i < HID*HID/4; i += NT) d2[i] = w2[i];
    }

    ull b1p[4], b2p[4];
    {
        float4 ba = *(const float4*)(ib1 + c0);
        float4 bb = *(const float4*)(ib1 + c0 + 4);
        b1p[0] = pack2(ba.x, ba.y); b1p[1] = pack2(ba.z, ba.w);
        b1p[2] = pack2(bb.x, bb.y); b1p[3] = pack2(bb.z, bb.w);
        ba = *(const float4*)(ib2 + c0);
        bb = *(const float4*)(ib2 + c0 + 4);
        b2p[0] = pack2(ba.x, ba.y); b2p[1] = pack2(ba.z, ba.w);
        b2p[2] = pack2(bb.x, bb.y); b2p[3] = pack2(bb.z, bb.w);
    }

    while (true) {
        __syncthreads();
        if (tid == 0) s_tile = (int)atomicAdd(&g_ctr_node, 1u);
        __syncthreads();
        const int tile = s_tile;
        if (tile >= NTILES_N) break;
        const int nbase = tile * TILE;

        for (int idx = tid; idx < TILE * (HID/4); idx += NT) {
            int n  = idx & 127;
            int c4 = idx >> 7;
            float4 v = make_float4(0.f,0.f,0.f,0.f);
            int gn = nbase + n;
            if (gn < NNODES) v = __ldg((const float4*)(g_agg + gn*HID + c4*4));
            xT[(c4*4+0)*XTS + n] = v.x;
            xT[(c4*4+1)*XTS + n] = v.y;
            xT[(c4*4+2)*XTS + n] = v.z;
            xT[(c4*4+3)*XTS + n] = v.w;
        }
        __syncthreads();

        ull acc[16];
        #pragma unroll
        for (int e = 0; e < 4; e++) {
            acc[e*4+0]=b1p[0]; acc[e*4+1]=b1p[1]; acc[e*4+2]=b1p[2]; acc[e*4+3]=b1p[3];
        }
        for (int k = 0; k < HID; k += 4) {
            float4 av[4];
            ulonglong2 w01[4], w23[4];
            #pragma unroll
            for (int u = 0; u < 4; u++) {
                av[u] = *(const float4*)(xT + (k+u)*XTS + e0);
                const ulonglong2* wp = (const ulonglong2*)(iw1_s + (k+u)*HID + c0);
                w01[u] = wp[0]; w23[u] = wp[1];
            }
            #pragma unroll
            for (int u = 0; u < 4; u++) {
                ull a0 = bcast2(av[u].x), a1 = bcast2(av[u].y), a2 = bcast2(av[u].z), a3 = bcast2(av[u].w);
                fma2(acc[0],a0,w01[u].x);  fma2(acc[1],a0,w01[u].y);  fma2(acc[2],a0,w23[u].x);  fma2(acc[3],a0,w23[u].y);
                fma2(acc[4],a1,w01[u].x);  fma2(acc[5],a1,w01[u].y);  fma2(acc[6],a1,w23[u].x);  fma2(acc[7],a1,w23[u].y);
                fma2(acc[8],a2,w01[u].x);  fma2(acc[9],a2,w01[u].y);  fma2(acc[10],a2,w23[u].x); fma2(acc[11],a2,w23[u].y);
                fma2(acc[12],a3,w01[u].x); fma2(acc[13],a3,w01[u].y); fma2(acc[14],a3,w23[u].x); fma2(acc[15],a3,w23[u].y);
            }
        }
        __syncthreads();

        #pragma unroll
        for (int cp = 0; cp < 4; cp++) {
            float2 v0 = unpack2(acc[0*4+cp]);
            float2 v1 = unpack2(acc[1*4+cp]);
            float2 v2 = unpack2(acc[2*4+cp]);
            float2 v3 = unpack2(acc[3*4+cp]);
            float4 oA = make_float4(silu_f(v0.x), silu_f(v1.x), silu_f(v2.x), silu_f(v3.x));
            float4 oB = make_float4(silu_f(v0.y), silu_f(v1.y), silu_f(v2.y), silu_f(v3.y));
            *(float4*)(xT + (c0 + 2*cp    )*XTS + e0) = oA;
            *(float4*)(xT + (c0 + 2*cp + 1)*XTS + e0) = oB;
        }
        __syncthreads();

        #pragma unroll
        for (int e = 0; e < 4; e++) {
            acc[e*4+0]=b2p[0]; acc[e*4+1]=b2p[1]; acc[e*4+2]=b2p[2]; acc[e*4+3]=b2p[3];
        }
        for (int k = 0; k < HID; k += 4) {
            float4 av[4];
            ulonglong2 w01[4], w23[4];
            #pragma unroll
            for (int u = 0; u < 4; u++) {
                av[u] = *(const float4*)(xT + (k+u)*XTS + e0);
                const ulonglong2* wp = (const ulonglong2*)(iw2_s + (k+u)*HID + c0);
                w01[u] = wp[0]; w23[u] = wp[1];
            }
            #pragma unroll
            for (int u = 0; u < 4; u++) {
                ull a0 = bcast2(av[u].x), a1 = bcast2(av[u].y), a2 = bcast2(av[u].z), a3 = bcast2(av[u].w);
                fma2(acc[0],a0,w01[u].x);  fma2(acc[1],a0,w01[u].y);  fma2(acc[2],a0,w23[u].x);  fma2(acc[3],a0,w23[u].y);
                fma2(acc[4],a1,w01[u].x);  fma2(acc[5],a1,w01[u].y);  fma2(acc[6],a1,w23[u].x);  fma2(acc[7],a1,w23[u].y);
                fma2(acc[8],a2,w01[u].x);  fma2(acc[9],a2,w01[u].y);  fma2(acc[10],a2,w23[u].x); fma2(acc[11],a2,w23[u].y);
                fma2(acc[12],a3,w01[u].x); fma2(acc[13],a3,w01[u].y); fma2(acc[14],a3,w23[u].x); fma2(acc[15],a3,w23[u].y);
            }
        }

        #pragma unroll
        for (int e = 0; e < 4; e++) {
            int n = nbase + e0 + e;
            if (n >= NNODES) continue;
            float4 h0 = __ldg((const float4*)(hin + n*HID + c0));
            float4 h1 = __ldg((const float4*)(hin + n*HID + c0 + 4));
            float2 v0 = unpack2(acc[e*4+0]);
            float2 v1 = unpack2(acc[e*4+1]);
            float2 v2 = unpack2(acc[e*4+2]);
            float2 v3 = unpack2(acc[e*4+3]);
            float4 o0 = make_float4(h0.x + v0.x, h0.y + v0.y, h0.z + v1.x, h0.w + v1.y);
            float4 o1 = make_float4(h1.x + v2.x, h1.y + v2.y, h1.z + v3.x, h1.w + v3.y);
            *(float4*)(out + n*HID + c0)     = o0;
            *(float4*)(out + n*HID + c0 + 4) = o1;
        }
    }
}

extern "C" void kernel_launch(void* const* d_in, const int* in_sizes, int n_in,
                              void* d_out, int out_size)
{
    const float* h    = (const float*)d_in[0];
    const float* pos  = (const float*)d_in[1];
    const void*  ei   = d_in[2];
    const float* fw1  = (const float*)d_in[3];
    const float* fb1  = (const float*)d_in[4];
    const float* fw2  = (const float*)d_in[5];
    const float* fb2  = (const float*)d_in[6];
    const float* iw1  = (const float*)d_in[7];
    const float* ib1  = (const float*)d_in[8];
    const float* iw2  = (const float*)d_in[9];
    const float* ib2  = (const float*)d_in[10];
    float* out = (float*)d_out;

    cudaFuncSetAttribute(table_kernel, cudaFuncAttributeMaxDynamicSharedMemorySize, TBL_SMEM_BYTES);
    cudaFuncSetAttribute(node_kernel, cudaFuncAttributeMaxDynamicSharedMemorySize, NODE_SMEM_BYTES);

    zero_kernel<<<1184, 512>>>(ei);
    table_kernel<<<NBINS / TILE, NT, TBL_SMEM_BYTES>>>(fw1, fb1, fw2, fb2);
    htab_kernel<<<(NBINS * HID + 255) / 256, 256>>>();
    gather_kernel<<<GGRID, GNT>>>(h, pos, ei);
    node_kernel<<<GRID_P, NT, NODE_SMEM_BYTES>>>(h, out, iw1, ib1, iw2, ib2);
}

// round 10
// speedup vs baseline: 1.2179x; 1.0618x over previous
#include <cuda_runtime.h>
#include <cuda_fp16.h>
#include <cuda_bf16.h>
#include <cstdint>

#define NNODES  50000
#define NEDGES  640000
#define HID     128
#define NRBF    50
#define TILE    128
#define NT      512
#define CUTOFF_F 5.0f

#define NBINS   4096
#define TSTEP   (CUTOFF_F / (float)(NBINS - 1))
#define TINV    ((float)(NBINS - 1) / CUTOFF_F)

#define RBF_W   (CUTOFF_F / 49.0f)
#define RBF_IW  (49.0f / CUTOFF_F)

typedef unsigned long long ull;

__device__ float   g_agg[NNODES * HID];
__device__ float   g_table[NBINS * HID];
__device__ __half2 g_htab[NBINS * HID];
__device__ __align__(16) unsigned char g_wts[131072];  // [w1h|w1l|w2h|w2l] plain [k][n] bf16
__device__ int g_is64;

// ---------- packed f32x2 helpers (table kernel) ----------
__device__ __forceinline__ void fma2(ull &acc, ull a, ull b) {
    asm("fma.rn.f32x2 %0, %1, %2, %0;" : "+l"(acc) : "l"(a), "l"(b));
}
__device__ __forceinline__ ull bcast2(float x) {
    ull r; asm("mov.b64 %0, {%1, %1};" : "=l"(r) : "f"(x)); return r;
}
__device__ __forceinline__ ull pack2(float x, float y) {
    ull r; asm("mov.b64 %0, {%1, %2};" : "=l"(r) : "f"(x), "f"(y)); return r;
}
__device__ __forceinline__ float2 unpack2(ull v) {
    float2 f; asm("mov.b64 {%0, %1}, %2;" : "=f"(f.x), "=f"(f.y) : "l"(v)); return f;
}
__device__ __forceinline__ void red4(float* p, float a, float b, float c, float d) {
    asm volatile("red.global.add.v4.f32 [%0], {%1,%2,%3,%4};"
                 :: "l"(p), "f"(a), "f"(b), "f"(c), "f"(d) : "memory");
}
__device__ __forceinline__ float silu_f(float x) {
    return x / (1.0f + __expf(-x));
}

// ---------- mma helpers (baseline PTX, sm_80+) ----------
__device__ __forceinline__ uint32_t smem_u32(const void* p) {
    uint32_t a;
    asm("{ .reg .u64 t; cvta.to.shared.u64 t, %1; cvt.u32.u64 %0, t; }" : "=r"(a) : "l"(p));
    return a;
}
__device__ __forceinline__ void ldsm_x4(uint32_t &r0, uint32_t &r1, uint32_t &r2, uint32_t &r3, uint32_t a) {
    asm volatile("ldmatrix.sync.aligned.m8n8.x4.shared.b16 {%0,%1,%2,%3}, [%4];"
                 : "=r"(r0), "=r"(r1), "=r"(r2), "=r"(r3) : "r"(a));
}
__device__ __forceinline__ void ldsm_x4t(uint32_t &r0, uint32_t &r1, uint32_t &r2, uint32_t &r3, uint32_t a) {
    asm volatile("ldmatrix.sync.aligned.m8n8.x4.trans.shared.b16 {%0,%1,%2,%3}, [%4];"
                 : "=r"(r0), "=r"(r1), "=r"(r2), "=r"(r3) : "r"(a));
}
__device__ __forceinline__ void mma16816(float* d, uint32_t a0, uint32_t a1, uint32_t a2, uint32_t a3,
                                         uint32_t b0, uint32_t b1) {
    asm volatile("mma.sync.aligned.m16n8k16.row.col.f32.bf16.bf16.f32 "
                 "{%0,%1,%2,%3}, {%4,%5,%6,%7}, {%8,%9}, {%0,%1,%2,%3};"
                 : "+f"(d[0]), "+f"(d[1]), "+f"(d[2]), "+f"(d[3])
                 : "r"(a0), "r"(a1), "r"(a2), "r"(a3), "r"(b0), "r"(b1));
}

// ---------- zero scratch + dtype flag ----------
__global__ void zero_kernel(const void* ei) {
    if (blockIdx.x == 0 && threadIdx.x == 0) {
        const unsigned* u = (const unsigned*)ei;
        unsigned acc = 0;
        #pragma unroll
        for (int i = 0; i < 64; i++) acc |= u[2*i + 1];
        g_is64 = (acc == 0);
    }
    float4* p = (float4*)g_agg;
    const int n = NNODES * HID / 4;
    for (int i = blockIdx.x * blockDim.x + threadIdx.x; i < n; i += gridDim.x * blockDim.x)
        p[i] = make_float4(0.f, 0.f, 0.f, 0.f);
}

// ---------- weight prep: bf16 hi/lo split, plain [k][n] ----------
__global__ void wprep_kernel(const float* __restrict__ iw1, const float* __restrict__ iw2) {
    int idx = blockIdx.x * blockDim.x + threadIdx.x;
    if (idx >= HID * HID) return;
    float v1 = iw1[idx];
    __nv_bfloat16 h1 = __float2bfloat16(v1);
    __nv_bfloat16 l1 = __float2bfloat16(v1 - __bfloat162float(h1));
    *(__nv_bfloat16*)(g_wts + 0     + idx*2) = h1;
    *(__nv_bfloat16*)(g_wts + 32768 + idx*2) = l1;
    float v2 = iw2[idx];
    __nv_bfloat16 h2 = __float2bfloat16(v2);
    __nv_bfloat16 l2 = __float2bfloat16(v2 - __bfloat162float(h2));
    *(__nv_bfloat16*)(g_wts + 65536 + idx*2) = h2;
    *(__nv_bfloat16*)(g_wts + 98304 + idx*2) = l2;
}

// ---------- table build kernel (unchanged) ----------
#define TBL_SMEM_FLOATS (NRBF*HID + HID*HID + TILE*NRBF + TILE*HID + TILE)
#define TBL_SMEM_BYTES  (TBL_SMEM_FLOATS * 4)

__global__ __launch_bounds__(NT, 1)
void table_kernel(const float* __restrict__ fw1, const float* __restrict__ fb1,
                  const float* __restrict__ fw2, const float* __restrict__ fb2)
{
    extern __shared__ float sm[];
    float* fw1_s  = sm;
    float* fw2_s  = fw1_s + NRBF * HID;
    float* rbf_s  = fw2_s + HID * HID;
    float* s1_s   = rbf_s + TILE * NRBF;
    float* cut_s  = s1_s + TILE * HID;

    const int tid = threadIdx.x;
    const int rbase = blockIdx.x * TILE;

    {
        const float4* w1 = (const float4*)fw1; float4* d1 = (float4*)fw1_s;
        for (int i = tid; i < NRBF*HID/4; i += NT) d1[i] = w1[i];
        const float4* w2 = (const float4*)fw2; float4* d2 = (float4*)fw2_s;
        for (int i = tid; i < HID*HID/4; i += NT) d2[i] = w2[i];
    }
    if (tid < TILE) {
        float d = (float)(rbase + tid) * TSTEP;
        cut_s[tid] = 0.5f * (__cosf(d * (3.14159265358979323846f / CUTOFF_F)) + 1.0f);
    }
    for (int idx = tid; idx < TILE * NRBF; idx += NT) {
        int e = idx / NRBF;
        int k = idx - e * NRBF;
        float d = (float)(rbase + e) * TSTEP;
        float t = (d - (float)k * RBF_W) * RBF_IW;
        rbf_s[idx] = __expf(-0.5f * t * t);
    }
    __syncthreads();

    const int eg0 = (tid >> 4) * 4;
    const int c0  = (tid & 15) * 8;

    ull acc[4][4];
    {
        float4 ba = *(const float4*)(fb1 + c0);
        float4 bb = *(const float4*)(fb1 + c0 + 4);
        ull i0 = pack2(ba.x, ba.y), i1 = pack2(ba.z, ba.w);
        ull i2 = pack2(bb.x, bb.y), i3 = pack2(bb.z, bb.w);
        #pragma unroll
        for (int i = 0; i < 4; i++) { acc[i][0]=i0; acc[i][1]=i1; acc[i][2]=i2; acc[i][3]=i3; }
    }
    {
        const float* rb = rbf_s + eg0 * NRBF;
        #pragma unroll 2
        for (int k = 0; k < NRBF; k++) {
            ull a0 = bcast2(rb[k]);
            ull a1 = bcast2(rb[k +   NRBF]);
            ull a2 = bcast2(rb[k + 2*NRBF]);
            ull a3 = bcast2(rb[k + 3*NRBF]);
            const ulonglong2* wp = (const ulonglong2*)(fw1_s + k*HID + c0);
            ulonglong2 w01 = wp[0], w23 = wp[1];
            fma2(acc[0][0],a0,w01.x); fma2(acc[0][1],a0,w01.y); fma2(acc[0][2],a0,w23.x); fma2(acc[0][3],a0,w23.y);
            fma2(acc[1][0],a1,w01.x); fma2(acc[1][1],a1,w01.y); fma2(acc[1][2],a1,w23.x); fma2(acc[1][3],a1,w23.y);
            fma2(acc[2][0],a2,w01.x); fma2(acc[2][1],a2,w01.y); fma2(acc[2][2],a2,w23.x); fma2(acc[2][3],a2,w23.y);
            fma2(acc[3][0],a3,w01.x); fma2(acc[3][1],a3,w01.y); fma2(acc[3][2],a3,w23.x); fma2(acc[3][3],a3,w23.y);
        }
    }
    #pragma unroll
    for (int i = 0; i < 4; i++) {
        float4 o0, o1; float2 v;
        v = unpack2(acc[i][0]); o0.x = silu_f(v.x); o0.y = silu_f(v.y);
        v = unpack2(acc[i][1]); o0.z = silu_f(v.x); o0.w = silu_f(v.y);
        v = unpack2(acc[i][2]); o1.x = silu_f(v.x); o1.y = silu_f(v.y);
        v = unpack2(acc[i][3]); o1.z = silu_f(v.x); o1.w = silu_f(v.y);
        *(float4*)(s1_s + (eg0+i)*HID + c0)     = o0;
        *(float4*)(s1_s + (eg0+i)*HID + c0 + 4) = o1;
    }
    __syncthreads();

    {
        float4 ba = *(const float4*)(fb2 + c0);
        float4 bb = *(const float4*)(fb2 + c0 + 4);
        ull i0 = pack2(ba.x, ba.y), i1 = pack2(ba.z, ba.w);
        ull i2 = pack2(bb.x, bb.y), i3 = pack2(bb.z, bb.w);
        #pragma unroll
        for (int i = 0; i < 4; i++) { acc[i][0]=i0; acc[i][1]=i1; acc[i][2]=i2; acc[i][3]=i3; }
    }
    {
        const float* sb = s1_s + eg0 * HID;
        #pragma unroll 2
        for (int k = 0; k < HID; k++) {
            ull a0 = bcast2(sb[k]);
            ull a1 = bcast2(sb[k +   HID]);
            ull a2 = bcast2(sb[k + 2*HID]);
            ull a3 = bcast2(sb[k + 3*HID]);
            const ulonglong2* wp = (const ulonglong2*)(fw2_s + k*HID + c0);
            ulonglong2 w01 = wp[0], w23 = wp[1];
            fma2(acc[0][0],a0,w01.x); fma2(acc[0][1],a0,w01.y); fma2(acc[0][2],a0,w23.x); fma2(acc[0][3],a0,w23.y);
            fma2(acc[1][0],a1,w01.x); fma2(acc[1][1],a1,w01.y); fma2(acc[1][2],a1,w23.x); fma2(acc[1][3],a1,w23.y);
            fma2(acc[2][0],a2,w01.x); fma2(acc[2][1],a2,w01.y); fma2(acc[2][2],a2,w23.x); fma2(acc[2][3],a2,w23.y);
            fma2(acc[3][0],a3,w01.x); fma2(acc[3][1],a3,w01.y); fma2(acc[3][2],a3,w23.x); fma2(acc[3][3],a3,w23.y);
        }
    }
    #pragma unroll
    for (int i = 0; i < 4; i++) {
        int r = rbase + eg0 + i;
        float ct = cut_s[eg0 + i];
        float2 v0 = unpack2(acc[i][0]);
        float2 v1 = unpack2(acc[i][1]);
        float2 v2 = unpack2(acc[i][2]);
        float2 v3 = unpack2(acc[i][3]);
        float4 o0 = make_float4(v0.x*ct, v0.y*ct, v1.x*ct, v1.y*ct);
        float4 o1 = make_float4(v2.x*ct, v2.y*ct, v3.x*ct, v3.y*ct);
        *(float4*)(g_table + r*HID + c0)     = o0;
        *(float4*)(g_table + r*HID + c0 + 4) = o1;
    }
}

// ---------- interleaved fp16 {value, slope} table ----------
__global__ void htab_kernel() {
    int idx = blockIdx.x * blockDim.x + threadIdx.x;
    const int n = NBINS * HID;
    if (idx >= n) return;
    float v = g_table[idx];
    float s = (idx + HID < n) ? (g_table[idx + HID] - v) : 0.f;
    g_htab[idx] = __floats2half2_rn(v, s);
}

// ---------- edge gather/lerp/scatter (unchanged from R8) ----------
#define GNT 256
#define GGRID 1184

__global__ __launch_bounds__(GNT)
void gather_kernel(const float* __restrict__ hin, const float* __restrict__ pos,
                   const void* __restrict__ ei)
{
    const int is64 = g_is64;
    const int lane16 = threadIdx.x & 15;
    const int c0 = lane16 * 8;
    const int gpb = GNT / 16;
    int g = blockIdx.x * gpb + (threadIdx.x >> 4);
    const int gstride = GGRID * gpb;

    for (; g < NEDGES; g += gstride) {
        int r, c;
        if (is64) {
            r = (int)__ldg((const long long*)ei + g);
            c = (int)__ldg((const long long*)ei + NEDGES + g);
        } else {
            r = __ldg((const int*)ei + g);
            c = __ldg((const int*)ei + NEDGES + g);
        }
        float dx = pos[r*3+0] - pos[c*3+0];
        float dy = pos[r*3+1] - pos[c*3+1];
        float dz = pos[r*3+2] - pos[c*3+2];
        float d  = sqrtf(dx*dx + dy*dy + dz*dz + 1e-8f);
        if (d > CUTOFF_F) continue;

        float t = d * TINV;
        int i0 = (int)t;
        if (i0 > NBINS - 1) i0 = NBINS - 1;
        float fr = t - (float)i0;

        const uint4* Tp = (const uint4*)(g_htab + i0*HID + c0);
        uint4 q0 = Tp[0];
        uint4 q1 = Tp[1];
        float4 h0 = *(const float4*)(hin + c*HID + c0);
        float4 h1 = *(const float4*)(hin + c*HID + c0 + 4);

        float2 t0 = __half22float2(*(__half2*)&q0.x);
        float2 t1 = __half22float2(*(__half2*)&q0.y);
        float2 t2 = __half22float2(*(__half2*)&q0.z);
        float2 t3 = __half22float2(*(__half2*)&q0.w);
        float2 t4 = __half22float2(*(__half2*)&q1.x);
        float2 t5 = __half22float2(*(__half2*)&q1.y);
        float2 t6 = __half22float2(*(__half2*)&q1.z);
        float2 t7 = __half22float2(*(__half2*)&q1.w);

        float w0 = fmaf(fr, t0.y, t0.x);
        float w1 = fmaf(fr, t1.y, t1.x);
        float w2 = fmaf(fr, t2.y, t2.x);
        float w3 = fmaf(fr, t3.y, t3.x);
        float w4 = fmaf(fr, t4.y, t4.x);
        float w5 = fmaf(fr, t5.y, t5.x);
        float w6 = fmaf(fr, t6.y, t6.x);
        float w7 = fmaf(fr, t7.y, t7.x);

        float* dst = g_agg + r*HID + c0;
        red4(dst,     h0.x*w0, h0.y*w1, h0.z*w2, h0.w*w3);
        red4(dst + 4, h1.x*w4, h1.y*w5, h1.z*w6, h1.w*w7);
    }
}

// ---------- node kernel: mma.sync bf16 3-way split ----------
#define P3      136                     // row pitch in bf16 elements (272 B, conflict-free ldmatrix)
#define P3B     (P3 * 2)
#define T3B     (128 * P3B)             // 34816 B per tile
#define OFF_XH  0
#define OFF_XL  (T3B)
#define OFF_W1H (2 * T3B)
#define OFF_W1L (3 * T3B)
#define OFF_W2H (4 * T3B)
#define OFF_W2L (5 * T3B)
#define OFF_SB1 (6 * T3B)
#define OFF_SB2 (6 * T3B + 512)
#define NODE3_SMEM (6 * T3B + 1024)     // 209920 B
#define NODE3_GRID ((NNODES + TILE - 1) / TILE)

__global__ void __launch_bounds__(256, 1)
node3_kernel(const float* __restrict__ hin, float* __restrict__ outp,
             const float* __restrict__ ib1, const float* __restrict__ ib2)
{
    extern __shared__ unsigned char sm3[];
    const uint32_t sbu = smem_u32(sm3);
    float* sb1 = (float*)(sm3 + OFF_SB1);
    float* sb2 = (float*)(sm3 + OFF_SB2);

    const int tid  = threadIdx.x;
    const int wid  = tid >> 5;
    const int lane = tid & 31;
    const int nbase = blockIdx.x * TILE;

    // stage weights (4 tiles x 128 rows x 256B) into pitched smem
    {
        const int WOFF[4] = {OFF_W1H, OFF_W1L, OFF_W2H, OFF_W2L};
        for (int i = tid; i < 4 * 128 * 16; i += 256) {
            int t   = i >> 11;
            int rem = i & 2047;
            int row = rem >> 4;
            int q   = rem & 15;
            uint4 v = *(const uint4*)(g_wts + t * 32768 + row * 256 + q * 16);
            *(uint4*)(sm3 + WOFF[t] + row * P3B + q * 16) = v;
        }
    }
    if (tid < 128) { sb1[tid] = ib1[tid]; sb2[tid] = ib2[tid]; }

    // stage x = agg tile, hi/lo bf16 split, pitched
    for (int idx = tid; idx < 128 * 32; idx += 256) {
        int n  = idx >> 5;
        int c4 = (idx & 31) << 2;
        float4 v = make_float4(0.f, 0.f, 0.f, 0.f);
        if (nbase + n < NNODES) v = __ldg((const float4*)(g_agg + (nbase + n) * HID + c4));
        __nv_bfloat16 hx = __float2bfloat16(v.x), hy = __float2bfloat16(v.y);
        __nv_bfloat16 hz = __float2bfloat16(v.z), hw = __float2bfloat16(v.w);
        __nv_bfloat16 lx = __float2bfloat16(v.x - __bfloat162float(hx));
        __nv_bfloat16 ly = __float2bfloat16(v.y - __bfloat162float(hy));
        __nv_bfloat16 lz = __float2bfloat16(v.z - __bfloat162float(hz));
        __nv_bfloat16 lw = __float2bfloat16(v.w - __bfloat162float(hw));
        int o = n * P3B + c4 * 2;
        *(__nv_bfloat162*)(sm3 + OFF_XH + o)     = __halves2bfloat162(hx, hy);
        *(__nv_bfloat162*)(sm3 + OFF_XH + o + 4) = __halves2bfloat162(hz, hw);
        *(__nv_bfloat162*)(sm3 + OFF_XL + o)     = __halves2bfloat162(lx, ly);
        *(__nv_bfloat162*)(sm3 + OFF_XL + o + 4) = __halves2bfloat162(lz, lw);
    }
    __syncthreads();

    const int mbase = wid << 4;           // warp owns rows [mbase, mbase+16)
    const int g  = lane >> 2;
    const int tg = lane & 3;
    // per-lane ldmatrix address components
    const uint32_t lrow = (lane & 15);
    const uint32_t lcol = ((lane >> 4) & 1) << 4;   // byte offset (8 elems * 2B)

    float acc[64];

    // ================= GEMM1: s1 = silu(x @ iw1 + b1) =================
    #pragma unroll
    for (int i = 0; i < 64; i++) acc[i] = 0.f;
    #pragma unroll
    for (int pass = 0; pass < 3; pass++) {
        const int aoff = (pass == 2) ? OFF_XL  : OFF_XH;
        const int boff = (pass == 1) ? OFF_W1L : OFF_W1H;
        const uint32_t abase = sbu + aoff + (mbase + lrow) * P3B + lcol;
        const uint32_t bbase = sbu + boff + lrow * P3B + lcol;
        #pragma unroll
        for (int k8 = 0; k8 < 8; k8++) {
            uint32_t a0, a1, a2, a3;
            ldsm_x4(a0, a1, a2, a3, abase + k8 * 32);
            uint32_t bb = bbase + (uint32_t)(k8 * 16) * P3B;
            #pragma unroll
            for (int nb2 = 0; nb2 < 8; nb2++) {
                uint32_t b0, b1, b2, b3;
                ldsm_x4t(b0, b1, b2, b3, bb + nb2 * 32);
                mma16816(acc + nb2 * 8,     a0, a1, a2, a3, b0, b1);
                mma16816(acc + nb2 * 8 + 4, a0, a1, a2, a3, b2, b3);
            }
        }
    }
    __syncwarp();
    // epilogue 1: bias + silu + hi/lo split back into xh/xl (own strip only)
    {
        int r0 = mbase + g, r1 = r0 + 8;
        #pragma unroll
        for (int nb = 0; nb < 16; nb++) {
            int c = (nb << 3) + (tg << 1);
            float v0 = silu_f(acc[nb*4+0] + sb1[c]);
            float v1 = silu_f(acc[nb*4+1] + sb1[c+1]);
            float v2 = silu_f(acc[nb*4+2] + sb1[c]);
            float v3 = silu_f(acc[nb*4+3] + sb1[c+1]);
            __nv_bfloat16 h0 = __float2bfloat16(v0), h1 = __float2bfloat16(v1);
            __nv_bfloat16 h2 = __float2bfloat16(v2), h3 = __float2bfloat16(v3);
            __nv_bfloat16 l0 = __float2bfloat16(v0 - __bfloat162float(h0));
            __nv_bfloat16 l1 = __float2bfloat16(v1 - __bfloat162float(h1));
            __nv_bfloat16 l2 = __float2bfloat16(v2 - __bfloat162float(h2));
            __nv_bfloat16 l3 = __float2bfloat16(v3 - __bfloat162float(h3));
            *(__nv_bfloat162*)(sm3 + OFF_XH + r0 * P3B + c * 2) = __halves2bfloat162(h0, h1);
            *(__nv_bfloat162*)(sm3 + OFF_XL + r0 * P3B + c * 2) = __halves2bfloat162(l0, l1);
            *(__nv_bfloat162*)(sm3 + OFF_XH + r1 * P3B + c * 2) = __halves2bfloat162(h2, h3);
            *(__nv_bfloat162*)(sm3 + OFF_XL + r1 * P3B + c * 2) = __halves2bfloat162(l2, l3);
        }
    }
    __syncwarp();

    // ================= GEMM2: out = h + (s1 @ iw2 + b2) =================
    #pragma unroll
    for (int i = 0; i < 64; i++) acc[i] = 0.f;
    #pragma unroll
    for (int pass = 0; pass < 3; pass++) {
        const int aoff = (pass == 2) ? OFF_XL  : OFF_XH;
        const int boff = (pass == 1) ? OFF_W2L : OFF_W2H;
        const uint32_t abase = sbu + aoff + (mbase + lrow) * P3B + lcol;
        const uint32_t bbase = sbu + boff + lrow * P3B + lcol;
        #pragma unroll
        for (int k8 = 0; k8 < 8; k8++) {
            uint32_t a0, a1, a2, a3;
            ldsm_x4(a0, a1, a2, a3, abase + k8 * 32);
            uint32_t bb = bbase + (uint32_t)(k8 * 16) * P3B;
            #pragma unroll
            for (int nb2 = 0; nb2 < 8; nb2++) {
                uint32_t b0, b1, b2, b3;
                ldsm_x4t(b0, b1, b2, b3, bb + nb2 * 32);
                mma16816(acc + nb2 * 8,     a0, a1, a2, a3, b0, b1);
                mma16816(acc + nb2 * 8 + 4, a0, a1, a2, a3, b2, b3);
            }
        }
    }
    // epilogue 2
    {
        int n0 = nbase + mbase + g;
        int n1 = n0 + 8;
        #pragma unroll
        for (int nb = 0; nb < 16; nb++) {
            int c = (nb << 3) + (tg << 1);
            if (n0 < NNODES) {
                float2 hv = *(const float2*)(hin + n0 * HID + c);
                float2 o = make_float2(hv.x + acc[nb*4+0] + sb2[c],
                                       hv.y + acc[nb*4+1] + sb2[c+1]);
                *(float2*)(outp + n0 * HID + c) = o;
            }
            if (n1 < NNODES) {
                float2 hv = *(const float2*)(hin + n1 * HID + c);
                float2 o = make_float2(hv.x + acc[nb*4+2] + sb2[c],
                                       hv.y + acc[nb*4+3] + sb2[c+1]);
                *(float2*)(outp + n1 * HID + c) = o;
            }
        }
    }
}

extern "C" void kernel_launch(void* const* d_in, const int* in_sizes, int n_in,
                              void* d_out, int out_size)
{
    const float* h    = (const float*)d_in[0];
    const float* pos  = (const float*)d_in[1];
    const void*  ei   = d_in[2];
    const float* fw1  = (const float*)d_in[3];
    const float* fb1  = (const float*)d_in[4];
    const float* fw2  = (const float*)d_in[5];
    const float* fb2  = (const float*)d_in[6];
    const float* iw1  = (const float*)d_in[7];
    const float* ib1  = (const float*)d_in[8];
    const float* iw2  = (const float*)d_in[9];
    const float* ib2  = (const float*)d_in[10];
    float* out = (float*)d_out;

    cudaFuncSetAttribute(table_kernel, cudaFuncAttributeMaxDynamicSharedMemorySize, TBL_SMEM_BYTES);
    cudaFuncSetAttribute(node3_kernel, cudaFuncAttributeMaxDynamicSharedMemorySize, NODE3_SMEM);

    zero_kernel<<<1184, 512>>>(ei);
    wprep_kernel<<<(HID * HID + 255) / 256, 256>>>(iw1, iw2);
    table_kernel<<<NBINS / TILE, NT, TBL_SMEM_BYTES>>>(fw1, fb1, fw2, fb2);
    htab_kernel<<<(NBINS * HID + 255) / 256, 256>>>();
    gather_kernel<<<GGRID, GNT>>>(h, pos, ei);
    node3_kernel<<<NODE3_GRID, 256, NODE3_SMEM>>>(h, out, ib1, ib2);
}

// round 11
// speedup vs baseline: 1.6023x; 1.3156x over previous
#include <cuda_runtime.h>
#include <cuda_fp16.h>
#include <cuda_bf16.h>
#include <cstdint>

#define NNODES  50000
#define NEDGES  640000
#define HID     128
#define NRBF    50
#define TILE    128
#define NT      512
#define CUTOFF_F 5.0f

#define NBINS   4096
#define TSTEP   (CUTOFF_F / (float)(NBINS - 1))
#define TINV    ((float)(NBINS - 1) / CUTOFF_F)

#define RBF_W   (CUTOFF_F / 49.0f)
#define RBF_IW  (49.0f / CUTOFF_F)

#define CAP     48      // per-node bucket capacity (Poisson(12.8); P(overflow)~3e-8)

typedef unsigned long long ull;

__device__ float   g_agg[NNODES * HID];
__device__ float   g_table[NBINS * HID];
__device__ __half2 g_htab[NBINS * HID];
__device__ __align__(16) unsigned char g_wts[131072];  // [w1h|w1l|w2h|w2l] plain [k][n] bf16
__device__ int     g_cnt[NNODES];
__device__ int2    g_rec[NNODES * CAP];                // {col, t bits}
__device__ int g_is64;

// ---------- packed f32x2 helpers (table kernel) ----------
__device__ __forceinline__ void fma2(ull &acc, ull a, ull b) {
    asm("fma.rn.f32x2 %0, %1, %2, %0;" : "+l"(acc) : "l"(a), "l"(b));
}
__device__ __forceinline__ ull bcast2(float x) {
    ull r; asm("mov.b64 %0, {%1, %1};" : "=l"(r) : "f"(x)); return r;
}
__device__ __forceinline__ ull pack2(float x, float y) {
    ull r; asm("mov.b64 %0, {%1, %2};" : "=l"(r) : "f"(x), "f"(y)); return r;
}
__device__ __forceinline__ float2 unpack2(ull v) {
    float2 f; asm("mov.b64 {%0, %1}, %2;" : "=f"(f.x), "=f"(f.y) : "l"(v)); return f;
}
__device__ __forceinline__ float silu_f(float x) {
    return x / (1.0f + __expf(-x));
}

// ---------- mma helpers (baseline PTX, sm_80+) ----------
__device__ __forceinline__ uint32_t smem_u32(const void* p) {
    uint32_t a;
    asm("{ .reg .u64 t; cvta.to.shared.u64 t, %1; cvt.u32.u64 %0, t; }" : "=r"(a) : "l"(p));
    return a;
}
__device__ __forceinline__ void ldsm_x4(uint32_t &r0, uint32_t &r1, uint32_t &r2, uint32_t &r3, uint32_t a) {
    asm volatile("ldmatrix.sync.aligned.m8n8.x4.shared.b16 {%0,%1,%2,%3}, [%4];"
                 : "=r"(r0), "=r"(r1), "=r"(r2), "=r"(r3) : "r"(a));
}
__device__ __forceinline__ void ldsm_x4t(uint32_t &r0, uint32_t &r1, uint32_t &r2, uint32_t &r3, uint32_t a) {
    asm volatile("ldmatrix.sync.aligned.m8n8.x4.trans.shared.b16 {%0,%1,%2,%3}, [%4];"
                 : "=r"(r0), "=r"(r1), "=r"(r2), "=r"(r3) : "r"(a));
}
__device__ __forceinline__ void mma16816(float* d, uint32_t a0, uint32_t a1, uint32_t a2, uint32_t a3,
                                         uint32_t b0, uint32_t b1) {
    asm volatile("mma.sync.aligned.m16n8k16.row.col.f32.bf16.bf16.f32 "
                 "{%0,%1,%2,%3}, {%4,%5,%6,%7}, {%8,%9}, {%0,%1,%2,%3};"
                 : "+f"(d[0]), "+f"(d[1]), "+f"(d[2]), "+f"(d[3])
                 : "r"(a0), "r"(a1), "r"(a2), "r"(a3), "r"(b0), "r"(b1));
}

// ---------- init: zero bucket counters + dtype flag ----------
__global__ void init_kernel(const void* ei) {
    if (blockIdx.x == 0 && threadIdx.x == 0) {
        const unsigned* u = (const unsigned*)ei;
        unsigned acc = 0;
        #pragma unroll
        for (int i = 0; i < 64; i++) acc |= u[2*i + 1];
        g_is64 = (acc == 0);
    }
    for (int i = blockIdx.x * blockDim.x + threadIdx.x; i < NNODES; i += gridDim.x * blockDim.x)
        g_cnt[i] = 0;
}

// ---------- scatter edges into per-node buckets (single pass) ----------
#define GNT 256
#define GGRID 1184

__global__ __launch_bounds__(GNT)
void scatter_kernel(const float* __restrict__ pos, const void* __restrict__ ei) {
    const int is64 = g_is64;
    for (int g = blockIdx.x * blockDim.x + threadIdx.x; g < NEDGES; g += gridDim.x * blockDim.x) {
        int r, c;
        if (is64) {
            r = (int)__ldg((const long long*)ei + g);
            c = (int)__ldg((const long long*)ei + NEDGES + g);
        } else {
            r = __ldg((const int*)ei + g);
            c = __ldg((const int*)ei + NEDGES + g);
        }
        float dx = pos[r*3+0] - pos[c*3+0];
        float dy = pos[r*3+1] - pos[c*3+1];
        float dz = pos[r*3+2] - pos[c*3+2];
        float d  = sqrtf(dx*dx + dy*dy + dz*dz + 1e-8f);
        if (d > CUTOFF_F) continue;
        float t = d * TINV;
        if (t > (float)(NBINS - 1)) t = (float)(NBINS - 1);
        int slot = atomicAdd(&g_cnt[r], 1);
        if (slot < CAP)
            g_rec[r * CAP + slot] = make_int2(c, __float_as_int(t));
    }
}

// ---------- weight prep: bf16 hi/lo split, plain [k][n] ----------
__global__ void wprep_kernel(const float* __restrict__ iw1, const float* __restrict__ iw2) {
    int idx = blockIdx.x * blockDim.x + threadIdx.x;
    if (idx >= HID * HID) return;
    float v1 = iw1[idx];
    __nv_bfloat16 h1 = __float2bfloat16(v1);
    __nv_bfloat16 l1 = __float2bfloat16(v1 - __bfloat162float(h1));
    *(__nv_bfloat16*)(g_wts + 0     + idx*2) = h1;
    *(__nv_bfloat16*)(g_wts + 32768 + idx*2) = l1;
    float v2 = iw2[idx];
    __nv_bfloat16 h2 = __float2bfloat16(v2);
    __nv_bfloat16 l2 = __float2bfloat16(v2 - __bfloat162float(h2));
    *(__nv_bfloat16*)(g_wts + 65536 + idx*2) = h2;
    *(__nv_bfloat16*)(g_wts + 98304 + idx*2) = l2;
}

// ---------- table build kernel ----------
#define TBL_SMEM_FLOATS (NRBF*HID + HID*HID + TILE*NRBF + TILE*HID + TILE)
#define TBL_SMEM_BYTES  (TBL_SMEM_FLOATS * 4)

__global__ __launch_bounds__(NT, 1)
void table_kernel(const float* __restrict__ fw1, const float* __restrict__ fb1,
                  const float* __restrict__ fw2, const float* __restrict__ fb2)
{
    extern __shared__ float sm[];
    float* fw1_s  = sm;
    float* fw2_s  = fw1_s + NRBF * HID;
    float* rbf_s  = fw2_s + HID * HID;
    float* s1_s   = rbf_s + TILE * NRBF;
    float* cut_s  = s1_s + TILE * HID;

    const int tid = threadIdx.x;
    const int rbase = blockIdx.x * TILE;

    {
        const float4* w1 = (const float4*)fw1; float4* d1 = (float4*)fw1_s;
        for (int i = tid; i < NRBF*HID/4; i += NT) d1[i] = w1[i];
        const float4* w2 = (const float4*)fw2; float4* d2 = (float4*)fw2_s;
        for (int i = tid; i < HID*HID/4; i += NT) d2[i] = w2[i];
    }
    if (tid < TILE) {
        float d = (float)(rbase + tid) * TSTEP;
        cut_s[tid] = 0.5f * (__cosf(d * (3.14159265358979323846f / CUTOFF_F)) + 1.0f);
    }
    for (int idx = tid; idx < TILE * NRBF; idx += NT) {
        int e = idx / NRBF;
        int k = idx - e * NRBF;
        float d = (float)(rbase + e) * TSTEP;
        float t = (d - (float)k * RBF_W) * RBF_IW;
        rbf_s[idx] = __expf(-0.5f * t * t);
    }
    __syncthreads();

    const int eg0 = (tid >> 4) * 4;
    const int c0  = (tid & 15) * 8;

    ull acc[4][4];
    {
        float4 ba = *(const float4*)(fb1 + c0);
        float4 bb = *(const float4*)(fb1 + c0 + 4);
        ull i0 = pack2(ba.x, ba.y), i1 = pack2(ba.z, ba.w);
        ull i2 = pack2(bb.x, bb.y), i3 = pack2(bb.z, bb.w);
        #pragma unroll
        for (int i = 0; i < 4; i++) { acc[i][0]=i0; acc[i][1]=i1; acc[i][2]=i2; acc[i][3]=i3; }
    }
    {
        const float* rb = rbf_s + eg0 * NRBF;
        #pragma unroll 2
        for (int k = 0; k < NRBF; k++) {
            ull a0 = bcast2(rb[k]);
            ull a1 = bcast2(rb[k +   NRBF]);
            ull a2 = bcast2(rb[k + 2*NRBF]);
            ull a3 = bcast2(rb[k + 3*NRBF]);
            const ulonglong2* wp = (const ulonglong2*)(fw1_s + k*HID + c0);
            ulonglong2 w01 = wp[0], w23 = wp[1];
            fma2(acc[0][0],a0,w01.x); fma2(acc[0][1],a0,w01.y); fma2(acc[0][2],a0,w23.x); fma2(acc[0][3],a0,w23.y);
            fma2(acc[1][0],a1,w01.x); fma2(acc[1][1],a1,w01.y); fma2(acc[1][2],a1,w23.x); fma2(acc[1][3],a1,w23.y);
            fma2(acc[2][0],a2,w01.x); fma2(acc[2][1],a2,w01.y); fma2(acc[2][2],a2,w23.x); fma2(acc[2][3],a2,w23.y);
            fma2(acc[3][0],a3,w01.x); fma2(acc[3][1],a3,w01.y); fma2(acc[3][2],a3,w23.x); fma2(acc[3][3],a3,w23.y);
        }
    }
    #pragma unroll
    for (int i = 0; i < 4; i++) {
        float4 o0, o1; float2 v;
        v = unpack2(acc[i][0]); o0.x = silu_f(v.x); o0.y = silu_f(v.y);
        v = unpack2(acc[i][1]); o0.z = silu_f(v.x); o0.w = silu_f(v.y);
        v = unpack2(acc[i][2]); o1.x = silu_f(v.x); o1.y = silu_f(v.y);
        v = unpack2(acc[i][3]); o1.z = silu_f(v.x); o1.w = silu_f(v.y);
        *(float4*)(s1_s + (eg0+i)*HID + c0)     = o0;
        *(float4*)(s1_s + (eg0+i)*HID + c0 + 4) = o1;
    }
    __syncthreads();

    {
        float4 ba = *(const float4*)(fb2 + c0);
        float4 bb = *(const float4*)(fb2 + c0 + 4);
        ull i0 = pack2(ba.x, ba.y), i1 = pack2(ba.z, ba.w);
        ull i2 = pack2(bb.x, bb.y), i3 = pack2(bb.z, bb.w);
        #pragma unroll
        for (int i = 0; i < 4; i++) { acc[i][0]=i0; acc[i][1]=i1; acc[i][2]=i2; acc[i][3]=i3; }
    }
    {
        const float* sb = s1_s + eg0 * HID;
        #pragma unroll 2
        for (int k = 0; k < HID; k++) {
            ull a0 = bcast2(sb[k]);
            ull a1 = bcast2(sb[k +   HID]);
            ull a2 = bcast2(sb[k + 2*HID]);
            ull a3 = bcast2(sb[k + 3*HID]);
            const ulonglong2* wp = (const ulonglong2*)(fw2_s + k*HID + c0);
            ulonglong2 w01 = wp[0], w23 = wp[1];
            fma2(acc[0][0],a0,w01.x); fma2(acc[0][1],a0,w01.y); fma2(acc[0][2],a0,w23.x); fma2(acc[0][3],a0,w23.y);
            fma2(acc[1][0],a1,w01.x); fma2(acc[1][1],a1,w01.y); fma2(acc[1][2],a1,w23.x); fma2(acc[1][3],a1,w23.y);
            fma2(acc[2][0],a2,w01.x); fma2(acc[2][1],a2,w01.y); fma2(acc[2][2],a2,w23.x); fma2(acc[2][3],a2,w23.y);
            fma2(acc[3][0],a3,w01.x); fma2(acc[3][1],a3,w01.y); fma2(acc[3][2],a3,w23.x); fma2(acc[3][3],a3,w23.y);
        }
    }
    #pragma unroll
    for (int i = 0; i < 4; i++) {
        int r = rbase + eg0 + i;
        float ct = cut_s[eg0 + i];
        float2 v0 = unpack2(acc[i][0]);
        float2 v1 = unpack2(acc[i][1]);
        float2 v2 = unpack2(acc[i][2]);
        float2 v3 = unpack2(acc[i][3]);
        float4 o0 = make_float4(v0.x*ct, v0.y*ct, v1.x*ct, v1.y*ct);
        float4 o1 = make_float4(v2.x*ct, v2.y*ct, v3.x*ct, v3.y*ct);
        *(float4*)(g_table + r*HID + c0)     = o0;
        *(float4*)(g_table + r*HID + c0 + 4) = o1;
    }
}

// ---------- interleaved fp16 {value, slope} table ----------
__global__ void htab_kernel() {
    int idx = blockIdx.x * blockDim.x + threadIdx.x;
    const int n = NBINS * HID;
    if (idx >= n) return;
    float v = g_table[idx];
    float s = (idx + HID < n) ? (g_table[idx + HID] - v) : 0.f;
    g_htab[idx] = __floats2half2_rn(v, s);
}

// ---------- CSR gather: one warp per node, no atomics ----------
__global__ __launch_bounds__(GNT)
void gather_kernel(const float* __restrict__ hin)
{
    const int lane = threadIdx.x & 31;
    const int c0 = lane * 4;
    int n = (blockIdx.x * GNT + threadIdx.x) >> 5;
    const int nstride = (GGRID * GNT) >> 5;

    for (; n < NNODES; n += nstride) {
        int cnt = __ldg(&g_cnt[n]);
        if (cnt > CAP) cnt = CAP;
        const int2* recs = g_rec + n * CAP;
        float4 acc = make_float4(0.f, 0.f, 0.f, 0.f);

        #pragma unroll 2
        for (int e = 0; e < cnt; e++) {
            int2 rec = __ldg(&recs[e]);              // broadcast across warp
            float t = __int_as_float(rec.y);
            int i0 = (int)t;
            float fr = t - (float)i0;

            uint4 q = *(const uint4*)(g_htab + i0*HID + c0);   // 4 ch {v,s}
            float4 hv = __ldg((const float4*)(hin + rec.x*HID + c0));

            float2 t0 = __half22float2(*(__half2*)&q.x);
            float2 t1 = __half22float2(*(__half2*)&q.y);
            float2 t2 = __half22float2(*(__half2*)&q.z);
            float2 t3 = __half22float2(*(__half2*)&q.w);

            acc.x = fmaf(hv.x, fmaf(fr, t0.y, t0.x), acc.x);
            acc.y = fmaf(hv.y, fmaf(fr, t1.y, t1.x), acc.y);
            acc.z = fmaf(hv.z, fmaf(fr, t2.y, t2.x), acc.z);
            acc.w = fmaf(hv.w, fmaf(fr, t3.y, t3.x), acc.w);
        }
        *(float4*)(g_agg + n*HID + c0) = acc;
    }
}

// ---------- node kernel: mma.sync bf16 3-way split (unchanged from R10) ----------
#define P3      136
#define P3B     (P3 * 2)
#define T3B     (128 * P3B)
#define OFF_XH  0
#define OFF_XL  (T3B)
#define OFF_W1H (2 * T3B)
#define OFF_W1L (3 * T3B)
#define OFF_W2H (4 * T3B)
#define OFF_W2L (5 * T3B)
#define OFF_SB1 (6 * T3B)
#define OFF_SB2 (6 * T3B + 512)
#define NODE3_SMEM (6 * T3B + 1024)
#define NODE3_GRID ((NNODES + TILE - 1) / TILE)

__global__ void __launch_bounds__(256, 1)
node3_kernel(const float* __restrict__ hin, float* __restrict__ outp,
             const float* __restrict__ ib1, const float* __restrict__ ib2)
{
    extern __shared__ unsigned char sm3[];
    const uint32_t sbu = smem_u32(sm3);
    float* sb1 = (float*)(sm3 + OFF_SB1);
    float* sb2 = (float*)(sm3 + OFF_SB2);

    const int tid  = threadIdx.x;
    const int wid  = tid >> 5;
    const int lane = tid & 31;
    const int nbase = blockIdx.x * TILE;

    {
        const int WOFF[4] = {OFF_W1H, OFF_W1L, OFF_W2H, OFF_W2L};
        for (int i = tid; i < 4 * 128 * 16; i += 256) {
            int t   = i >> 11;
            int rem = i & 2047;
            int row = rem >> 4;
            int q   = rem & 15;
            uint4 v = *(const uint4*)(g_wts + t * 32768 + row * 256 + q * 16);
            *(uint4*)(sm3 + WOFF[t] + row * P3B + q * 16) = v;
        }
    }
    if (tid < 128) { sb1[tid] = ib1[tid]; sb2[tid] = ib2[tid]; }

    for (int idx = tid; idx < 128 * 32; idx += 256) {
        int n  = idx >> 5;
        int c4 = (idx & 31) << 2;
        float4 v = make_float4(0.f, 0.f, 0.f, 0.f);
        if (nbase + n < NNODES) v = __ldg((const float4*)(g_agg + (nbase + n) * HID + c4));
        __nv_bfloat16 hx = __float2bfloat16(v.x), hy = __float2bfloat16(v.y);
        __nv_bfloat16 hz = __float2bfloat16(v.z), hw = __float2bfloat16(v.w);
        __nv_bfloat16 lx = __float2bfloat16(v.x - __bfloat162float(hx));
        __nv_bfloat16 ly = __float2bfloat16(v.y - __bfloat162float(hy));
        __nv_bfloat16 lz = __float2bfloat16(v.z - __bfloat162float(hz));
        __nv_bfloat16 lw = __float2bfloat16(v.w - __bfloat162float(hw));
        int o = n * P3B + c4 * 2;
        *(__nv_bfloat162*)(sm3 + OFF_XH + o)     = __halves2bfloat162(hx, hy);
        *(__nv_bfloat162*)(sm3 + OFF_XH + o + 4) = __halves2bfloat162(hz, hw);
        *(__nv_bfloat162*)(sm3 + OFF_XL + o)     = __halves2bfloat162(lx, ly);
        *(__nv_bfloat162*)(sm3 + OFF_XL + o + 4) = __halves2bfloat162(lz, lw);
    }
    __syncthreads();

    const int mbase = wid << 4;
    const int g  = lane >> 2;
    const int tg = lane & 3;
    const uint32_t lrow = (lane & 15);
    const uint32_t lcol = ((lane >> 4) & 1) << 4;

    float acc[64];

    #pragma unroll
    for (int i = 0; i < 64; i++) acc[i] = 0.f;
    #pragma unroll
    for (int pass = 0; pass < 3; pass++) {
        const int aoff = (pass == 2) ? OFF_XL  : OFF_XH;
        const int boff = (pass == 1) ? OFF_W1L : OFF_W1H;
        const uint32_t abase = sbu + aoff + (mbase + lrow) * P3B + lcol;
        const uint32_t bbase = sbu + boff + lrow * P3B + lcol;
        #pragma unroll
        for (int k8 = 0; k8 < 8; k8++) {
            uint32_t a0, a1, a2, a3;
            ldsm_x4(a0, a1, a2, a3, abase + k8 * 32);
            uint32_t bb = bbase + (uint32_t)(k8 * 16) * P3B;
            #pragma unroll
            for (int nb2 = 0; nb2 < 8; nb2++) {
                uint32_t b0, b1, b2, b3;
                ldsm_x4t(b0, b1, b2, b3, bb + nb2 * 32);
                mma16816(acc + nb2 * 8,     a0, a1, a2, a3, b0, b1);
                mma16816(acc + nb2 * 8 + 4, a0, a1, a2, a3, b2, b3);
            }
        }
    }
    __syncwarp();
    {
        int r0 = mbase + g, r1 = r0 + 8;
        #pragma unroll
        for (int nb = 0; nb < 16; nb++) {
            int c = (nb << 3) + (tg << 1);
            float v0 = silu_f(acc[nb*4+0] + sb1[c]);
            float v1 = silu_f(acc[nb*4+1] + sb1[c+1]);
            float v2 = silu_f(acc[nb*4+2] + sb1[c]);
            float v3 = silu_f(acc[nb*4+3] + sb1[c+1]);
            __nv_bfloat16 h0 = __float2bfloat16(v0), h1 = __float2bfloat16(v1);
            __nv_bfloat16 h2 = __float2bfloat16(v2), h3 = __float2bfloat16(v3);
            __nv_bfloat16 l0 = __float2bfloat16(v0 - __bfloat162float(h0));
            __nv_bfloat16 l1 = __float2bfloat16(v1 - __bfloat162float(h1));
            __nv_bfloat16 l2 = __float2bfloat16(v2 - __bfloat162float(h2));
            __nv_bfloat16 l3 = __float2bfloat16(v3 - __bfloat162float(h3));
            *(__nv_bfloat162*)(sm3 + OFF_XH + r0 * P3B + c * 2) = __halves2bfloat162(h0, h1);
            *(__nv_bfloat162*)(sm3 + OFF_XL + r0 * P3B + c * 2) = __halves2bfloat162(l0, l1);
            *(__nv_bfloat162*)(sm3 + OFF_XH + r1 * P3B + c * 2) = __halves2bfloat162(h2, h3);
            *(__nv_bfloat162*)(sm3 + OFF_XL + r1 * P3B + c * 2) = __halves2bfloat162(l2, l3);
        }
    }
    __syncwarp();

    #pragma unroll
    for (int i = 0; i < 64; i++) acc[i] = 0.f;
    #pragma unroll
    for (int pass = 0; pass < 3; pass++) {
        const int aoff = (pass == 2) ? OFF_XL  : OFF_XH;
        const int boff = (pass == 1) ? OFF_W2L : OFF_W2H;
        const uint32_t abase = sbu + aoff + (mbase + lrow) * P3B + lcol;
        const uint32_t bbase = sbu + boff + lrow * P3B + lcol;
        #pragma unroll
        for (int k8 = 0; k8 < 8; k8++) {
            uint32_t a0, a1, a2, a3;
            ldsm_x4(a0, a1, a2, a3, abase + k8 * 32);
            uint32_t bb = bbase + (uint32_t)(k8 * 16) * P3B;
            #pragma unroll
            for (int nb2 = 0; nb2 < 8; nb2++) {
                uint32_t b0, b1, b2, b3;
                ldsm_x4t(b0, b1, b2, b3, bb + nb2 * 32);
                mma16816(acc + nb2 * 8,     a0, a1, a2, a3, b0, b1);
                mma16816(acc + nb2 * 8 + 4, a0, a1, a2, a3, b2, b3);
            }
        }
    }
    {
        int n0 = nbase + mbase + g;
        int n1 = n0 + 8;
        #pragma unroll
        for (int nb = 0; nb < 16; nb++) {
            int c = (nb << 3) + (tg << 1);
            if (n0 < NNODES) {
                float2 hv = *(const float2*)(hin + n0 * HID + c);
                float2 o = make_float2(hv.x + acc[nb*4+0] + sb2[c],
                                       hv.y + acc[nb*4+1] + sb2[c+1]);
                *(float2*)(outp + n0 * HID + c) = o;
            }
            if (n1 < NNODES) {
                float2 hv = *(const float2*)(hin + n1 * HID + c);
                float2 o = make_float2(hv.x + acc[nb*4+2] + sb2[c],
                                       hv.y + acc[nb*4+3] + sb2[c+1]);
                *(float2*)(outp + n1 * HID + c) = o;
            }
        }
    }
}

extern "C" void kernel_launch(void* const* d_in, const int* in_sizes, int n_in,
                              void* d_out, int out_size)
{
    const float* h    = (const float*)d_in[0];
    const float* pos  = (const float*)d_in[1];
    const void*  ei   = d_in[2];
    const float* fw1  = (const float*)d_in[3];
    const float* fb1  = (const float*)d_in[4];
    const float* fw2  = (const float*)d_in[5];
    const float* fb2  = (const float*)d_in[6];
    const float* iw1  = (const float*)d_in[7];
    const float* ib1  = (const float*)d_in[8];
    const float* iw2  = (const float*)d_in[9];
    const float* ib2  = (const float*)d_in[10];
    float* out = (float*)d_out;

    cudaFuncSetAttribute(table_kernel, cudaFuncAttributeMaxDynamicSharedMemorySize, TBL_SMEM_BYTES);
    cudaFuncSetAttribute(node3_kernel, cudaFuncAttributeMaxDynamicSharedMemorySize, NODE3_SMEM);

    init_kernel<<<128, 512>>>(ei);
    scatter_kernel<<<GGRID, GNT>>>(pos, ei);
    wprep_kernel<<<(HID * HID + 255) / 256, 256>>>(iw1, iw2);
    table_kernel<<<NBINS / TILE, NT, TBL_SMEM_BYTES>>>(fw1, fb1, fw2, fb2);
    htab_kernel<<<(NBINS * HID + 255) / 256, 256>>>();
    gather_kernel<<<GGRID, GNT>>>(h);
    node3_kernel<<<NODE3_GRID, 256, NODE3_SMEM>>>(h, out, ib1, ib2);
}

// round 12
// speedup vs baseline: 1.7024x; 1.0625x over previous
#include <cuda_runtime.h>
#include <cuda_fp16.h>
#include <cuda_bf16.h>
#include <cstdint>

#define NNODES  50000
#define NEDGES  640000
#define HID     128
#define NRBF    50
#define TILE    128
#define NT      512
#define CUTOFF_F 5.0f

#define NBINS   4096
#define TSTEP   (CUTOFF_F / (float)(NBINS - 1))
#define TINV    ((float)(NBINS - 1) / CUTOFF_F)

#define RBF_W   (CUTOFF_F / 49.0f)
#define RBF_IW  (49.0f / CUTOFF_F)

#define CAP     48      // per-node bucket capacity (Poisson(12.8); P(overflow)~3e-8)

typedef unsigned long long ull;

__device__ float   g_agg[NNODES * HID];
__device__ float   g_table[NBINS * HID];
__device__ __half2 g_htab[NBINS * HID];
__device__ __align__(16) unsigned char g_wts[131072];  // [w1h|w1l|w2h|w2l] plain [k][n] bf16
__device__ int     g_cnt[NNODES];
__device__ int2    g_rec[NNODES * CAP];                // {col, t bits}
__device__ int g_is64;

// ---------- packed f32x2 helpers (table kernel) ----------
__device__ __forceinline__ void fma2(ull &acc, ull a, ull b) {
    asm("fma.rn.f32x2 %0, %1, %2, %0;" : "+l"(acc) : "l"(a), "l"(b));
}
__device__ __forceinline__ ull bcast2(float x) {
    ull r; asm("mov.b64 %0, {%1, %1};" : "=l"(r) : "f"(x)); return r;
}
__device__ __forceinline__ ull pack2(float x, float y) {
    ull r; asm("mov.b64 %0, {%1, %2};" : "=l"(r) : "f"(x), "f"(y)); return r;
}
__device__ __forceinline__ float2 unpack2(ull v) {
    float2 f; asm("mov.b64 {%0, %1}, %2;" : "=f"(f.x), "=f"(f.y) : "l"(v)); return f;
}
__device__ __forceinline__ float silu_f(float x) {
    return x / (1.0f + __expf(-x));
}

// ---------- mma helpers (baseline PTX, sm_80+) ----------
__device__ __forceinline__ uint32_t smem_u32(const void* p) {
    uint32_t a;
    asm("{ .reg .u64 t; cvta.to.shared.u64 t, %1; cvt.u32.u64 %0, t; }" : "=r"(a) : "l"(p));
    return a;
}
__device__ __forceinline__ void ldsm_x4(uint32_t &r0, uint32_t &r1, uint32_t &r2, uint32_t &r3, uint32_t a) {
    asm volatile("ldmatrix.sync.aligned.m8n8.x4.shared.b16 {%0,%1,%2,%3}, [%4];"
                 : "=r"(r0), "=r"(r1), "=r"(r2), "=r"(r3) : "r"(a));
}
__device__ __forceinline__ void ldsm_x4t(uint32_t &r0, uint32_t &r1, uint32_t &r2, uint32_t &r3, uint32_t a) {
    asm volatile("ldmatrix.sync.aligned.m8n8.x4.trans.shared.b16 {%0,%1,%2,%3}, [%4];"
                 : "=r"(r0), "=r"(r1), "=r"(r2), "=r"(r3) : "r"(a));
}
__device__ __forceinline__ void mma16816(float* d, uint32_t a0, uint32_t a1, uint32_t a2, uint32_t a3,
                                         uint32_t b0, uint32_t b1) {
    asm volatile("mma.sync.aligned.m16n8k16.row.col.f32.bf16.bf16.f32 "
                 "{%0,%1,%2,%3}, {%4,%5,%6,%7}, {%8,%9}, {%0,%1,%2,%3};"
                 : "+f"(d[0]), "+f"(d[1]), "+f"(d[2]), "+f"(d[3])
                 : "r"(a0), "r"(a1), "r"(a2), "r"(a3), "r"(b0), "r"(b1));
}

// ---------- merged init: zero counters + dtype flag + weight split ----------
__global__ void init_kernel(const void* ei, const float* __restrict__ iw1,
                            const float* __restrict__ iw2) {
    int idx = blockIdx.x * blockDim.x + threadIdx.x;
    if (idx == 0) {
        const unsigned* u = (const unsigned*)ei;
        unsigned acc = 0;
        #pragma unroll
        for (int i = 0; i < 64; i++) acc |= u[2*i + 1];
        g_is64 = (acc == 0);
    }
    for (int i = idx; i < NNODES; i += gridDim.x * blockDim.x)
        g_cnt[i] = 0;
    if (idx < HID * HID) {
        float v1 = iw1[idx];
        __nv_bfloat16 h1 = __float2bfloat16(v1);
        __nv_bfloat16 l1 = __float2bfloat16(v1 - __bfloat162float(h1));
        *(__nv_bfloat16*)(g_wts + 0     + idx*2) = h1;
        *(__nv_bfloat16*)(g_wts + 32768 + idx*2) = l1;
        float v2 = iw2[idx];
        __nv_bfloat16 h2 = __float2bfloat16(v2);
        __nv_bfloat16 l2 = __float2bfloat16(v2 - __bfloat162float(h2));
        *(__nv_bfloat16*)(g_wts + 65536 + idx*2) = h2;
        *(__nv_bfloat16*)(g_wts + 98304 + idx*2) = l2;
    }
}

// ---------- scatter edges into per-node buckets ----------
#define GNT 256
#define GGRID 1184

__global__ __launch_bounds__(GNT)
void scatter_kernel(const float* __restrict__ pos, const void* __restrict__ ei) {
    const int is64 = g_is64;
    for (int g = blockIdx.x * blockDim.x + threadIdx.x; g < NEDGES; g += gridDim.x * blockDim.x) {
        int r, c;
        if (is64) {
            r = (int)__ldg((const long long*)ei + g);
            c = (int)__ldg((const long long*)ei + NEDGES + g);
        } else {
            r = __ldg((const int*)ei + g);
            c = __ldg((const int*)ei + NEDGES + g);
        }
        float dx = pos[r*3+0] - pos[c*3+0];
        float dy = pos[r*3+1] - pos[c*3+1];
        float dz = pos[r*3+2] - pos[c*3+2];
        float d  = sqrtf(dx*dx + dy*dy + dz*dz + 1e-8f);
        if (d > CUTOFF_F) continue;
        float t = d * TINV;
        if (t > (float)(NBINS - 1)) t = (float)(NBINS - 1);
        int slot = atomicAdd(&g_cnt[r], 1);
        if (slot < CAP)
            g_rec[r * CAP + slot] = make_int2(c, __float_as_int(t));
    }
}

// ---------- table build kernel: 32 rows/CTA, grid = 128 (one full wave) ----------
#define TROWS 32
#define S1P   132
#define TBL_SMEM_FLOATS (NRBF*HID + HID*HID + TROWS*NRBF + TROWS*S1P + TROWS)
#define TBL_SMEM_BYTES  (TBL_SMEM_FLOATS * 4)

__global__ __launch_bounds__(NT, 1)
void table_kernel(const float* __restrict__ fw1, const float* __restrict__ fb1,
                  const float* __restrict__ fw2, const float* __restrict__ fb2)
{
    extern __shared__ float sm[];
    float* fw1_s  = sm;
    float* fw2_s  = fw1_s + NRBF * HID;
    float* rbf_s  = fw2_s + HID * HID;
    float* s1_s   = rbf_s + TROWS * NRBF;
    float* cut_s  = s1_s + TROWS * S1P;

    const int tid = threadIdx.x;
    const int rbase = blockIdx.x * TROWS;
    const int row = tid >> 4;          // 0..31
    const int c0  = (tid & 15) * 8;

    {
        const float4* w1 = (const float4*)fw1; float4* d1 = (float4*)fw1_s;
        for (int i = tid; i < NRBF*HID/4; i += NT) d1[i] = w1[i];
        const float4* w2 = (const float4*)fw2; float4* d2 = (float4*)fw2_s;
        for (int i = tid; i < HID*HID/4; i += NT) d2[i] = w2[i];
    }
    if (tid < TROWS) {
        float d = (float)(rbase + tid) * TSTEP;
        cut_s[tid] = 0.5f * (__cosf(d * (3.14159265358979323846f / CUTOFF_F)) + 1.0f);
    }
    for (int idx = tid; idx < TROWS * NRBF; idx += NT) {
        int e = idx / NRBF;
        int k = idx - e * NRBF;
        float d = (float)(rbase + e) * TSTEP;
        float t = (d - (float)k * RBF_W) * RBF_IW;
        rbf_s[idx] = __expf(-0.5f * t * t);
    }
    __syncthreads();

    // GEMM1 (k=50) + SiLU
    ull acc[4];
    {
        float4 ba = *(const float4*)(fb1 + c0);
        float4 bb = *(const float4*)(fb1 + c0 + 4);
        acc[0] = pack2(ba.x, ba.y); acc[1] = pack2(ba.z, ba.w);
        acc[2] = pack2(bb.x, bb.y); acc[3] = pack2(bb.z, bb.w);
    }
    {
        const float* rb = rbf_s + row * NRBF;
        #pragma unroll 5
        for (int k = 0; k < NRBF; k++) {
            ull a = bcast2(rb[k]);
            const ulonglong2* wp = (const ulonglong2*)(fw1_s + k*HID + c0);
            ulonglong2 w01 = wp[0], w23 = wp[1];
            fma2(acc[0], a, w01.x); fma2(acc[1], a, w01.y);
            fma2(acc[2], a, w23.x); fma2(acc[3], a, w23.y);
        }
    }
    {
        float4 o0, o1; float2 v;
        v = unpack2(acc[0]); o0.x = silu_f(v.x); o0.y = silu_f(v.y);
        v = unpack2(acc[1]); o0.z = silu_f(v.x); o0.w = silu_f(v.y);
        v = unpack2(acc[2]); o1.x = silu_f(v.x); o1.y = silu_f(v.y);
        v = unpack2(acc[3]); o1.z = silu_f(v.x); o1.w = silu_f(v.y);
        *(float4*)(s1_s + row*S1P + c0)     = o0;
        *(float4*)(s1_s + row*S1P + c0 + 4) = o1;
    }
    __syncthreads();

    // GEMM2 (k=128)
    {
        float4 ba = *(const float4*)(fb2 + c0);
        float4 bb = *(const float4*)(fb2 + c0 + 4);
        acc[0] = pack2(ba.x, ba.y); acc[1] = pack2(ba.z, ba.w);
        acc[2] = pack2(bb.x, bb.y); acc[3] = pack2(bb.z, bb.w);
    }
    {
        const float* sb = s1_s + row * S1P;
        #pragma unroll 4
        for (int k = 0; k < HID; k++) {
            ull a = bcast2(sb[k]);
            const ulonglong2* wp = (const ulonglong2*)(fw2_s + k*HID + c0);
            ulonglong2 w01 = wp[0], w23 = wp[1];
            fma2(acc[0], a, w01.x); fma2(acc[1], a, w01.y);
            fma2(acc[2], a, w23.x); fma2(acc[3], a, w23.y);
        }
    }
    {
        int r = rbase + row;
        float ct = cut_s[row];
        float2 v0 = unpack2(acc[0]);
        float2 v1 = unpack2(acc[1]);
        float2 v2 = unpack2(acc[2]);
        float2 v3 = unpack2(acc[3]);
        float4 o0 = make_float4(v0.x*ct, v0.y*ct, v1.x*ct, v1.y*ct);
        float4 o1 = make_float4(v2.x*ct, v2.y*ct, v3.x*ct, v3.y*ct);
        *(float4*)(g_table + r*HID + c0)     = o0;
        *(float4*)(g_table + r*HID + c0 + 4) = o1;
    }
}

// ---------- interleaved fp16 {value, slope} table ----------
__global__ void htab_kernel() {
    int idx = blockIdx.x * blockDim.x + threadIdx.x;
    const int n = NBINS * HID;
    if (idx >= n) return;
    float v = g_table[idx];
    float s = (idx + HID < n) ? (g_table[idx + HID] - v) : 0.f;
    g_htab[idx] = __floats2half2_rn(v, s);
}

// ---------- CSR gather: one warp per node, no atomics ----------
__global__ __launch_bounds__(GNT)
void gather_kernel(const float* __restrict__ hin)
{
    const int lane = threadIdx.x & 31;
    const int c0 = lane * 4;
    int n = (blockIdx.x * GNT + threadIdx.x) >> 5;
    const int nstride = (GGRID * GNT) >> 5;

    for (; n < NNODES; n += nstride) {
        int cnt = __ldg(&g_cnt[n]);
        if (cnt > CAP) cnt = CAP;
        const int2* recs = g_rec + n * CAP;
        float4 acc = make_float4(0.f, 0.f, 0.f, 0.f);

        #pragma unroll 2
        for (int e = 0; e < cnt; e++) {
            int2 rec = __ldg(&recs[e]);
            float t = __int_as_float(rec.y);
            int i0 = (int)t;
            float fr = t - (float)i0;

            uint4 q = *(const uint4*)(g_htab + i0*HID + c0);
            float4 hv = __ldg((const float4*)(hin + rec.x*HID + c0));

            float2 t0 = __half22float2(*(__half2*)&q.x);
            float2 t1 = __half22float2(*(__half2*)&q.y);
            float2 t2 = __half22float2(*(__half2*)&q.z);
            float2 t3 = __half22float2(*(__half2*)&q.w);

            acc.x = fmaf(hv.x, fmaf(fr, t0.y, t0.x), acc.x);
            acc.y = fmaf(hv.y, fmaf(fr, t1.y, t1.x), acc.y);
            acc.z = fmaf(hv.z, fmaf(fr, t2.y, t2.x), acc.z);
            acc.w = fmaf(hv.w, fmaf(fr, t3.y, t3.x), acc.w);
        }
        *(float4*)(g_agg + n*HID + c0) = acc;
    }
}

// ---------- node kernel: mma.sync bf16 3-way split (unchanged from R10) ----------
#define P3      136
#define P3B     (P3 * 2)
#define T3B     (128 * P3B)
#define OFF_XH  0
#define OFF_XL  (T3B)
#define OFF_W1H (2 * T3B)
#define OFF_W1L (3 * T3B)
#define OFF_W2H (4 * T3B)
#define OFF_W2L (5 * T3B)
#define OFF_SB1 (6 * T3B)
#define OFF_SB2 (6 * T3B + 512)
#define NODE3_SMEM (6 * T3B + 1024)
#define NODE3_GRID ((NNODES + TILE - 1) / TILE)

__global__ void __launch_bounds__(256, 1)
node3_kernel(const float* __restrict__ hin, float* __restrict__ outp,
             const float* __restrict__ ib1, const float* __restrict__ ib2)
{
    extern __shared__ unsigned char sm3[];
    const uint32_t sbu = smem_u32(sm3);
    float* sb1 = (float*)(sm3 + OFF_SB1);
    float* sb2 = (float*)(sm3 + OFF_SB2);

    const int tid  = threadIdx.x;
    const int wid  = tid >> 5;
    const int lane = tid & 31;
    const int nbase = blockIdx.x * TILE;

    {
        const int WOFF[4] = {OFF_W1H, OFF_W1L, OFF_W2H, OFF_W2L};
        for (int i = tid; i < 4 * 128 * 16; i += 256) {
            int t   = i >> 11;
            int rem = i & 2047;
            int row = rem >> 4;
            int q   = rem & 15;
            uint4 v = *(const uint4*)(g_wts + t * 32768 + row * 256 + q * 16);
            *(uint4*)(sm3 + WOFF[t] + row * P3B + q * 16) = v;
        }
    }
    if (tid < 128) { sb1[tid] = ib1[tid]; sb2[tid] = ib2[tid]; }

    for (int idx = tid; idx < 128 * 32; idx += 256) {
        int n  = idx >> 5;
        int c4 = (idx & 31) << 2;
        float4 v = make_float4(0.f, 0.f, 0.f, 0.f);
        if (nbase + n < NNODES) v = __ldg((const float4*)(g_agg + (nbase + n) * HID + c4));
        __nv_bfloat16 hx = __float2bfloat16(v.x), hy = __float2bfloat16(v.y);
        __nv_bfloat16 hz = __float2bfloat16(v.z), hw = __float2bfloat16(v.w);
        __nv_bfloat16 lx = __float2bfloat16(v.x - __bfloat162float(hx));
        __nv_bfloat16 ly = __float2bfloat16(v.y - __bfloat162float(hy));
        __nv_bfloat16 lz = __float2bfloat16(v.z - __bfloat162float(hz));
        __nv_bfloat16 lw = __float2bfloat16(v.w - __bfloat162float(hw));
        int o = n * P3B + c4 * 2;
        *(__nv_bfloat162*)(sm3 + OFF_XH + o)     = __halves2bfloat162(hx, hy);
        *(__nv_bfloat162*)(sm3 + OFF_XH + o + 4) = __halves2bfloat162(hz, hw);
        *(__nv_bfloat162*)(sm3 + OFF_XL + o)     = __halves2bfloat162(lx, ly);
        *(__nv_bfloat162*)(sm3 + OFF_XL + o + 4) = __halves2bfloat162(lz, lw);
    }
    __syncthreads();

    const int mbase = wid << 4;
    const int g  = lane >> 2;
    const int tg = lane & 3;
    const uint32_t lrow = (lane & 15);
    const uint32_t lcol = ((lane >> 4) & 1) << 4;

    float acc[64];

    #pragma unroll
    for (int i = 0; i < 64; i++) acc[i] = 0.f;
    #pragma unroll
    for (int pass = 0; pass < 3; pass++) {
        const int aoff = (pass == 2) ? OFF_XL  : OFF_XH;
        const int boff = (pass == 1) ? OFF_W1L : OFF_W1H;
        const uint32_t abase = sbu + aoff + (mbase + lrow) * P3B + lcol;
        const uint32_t bbase = sbu + boff + lrow * P3B + lcol;
        #pragma unroll
        for (int k8 = 0; k8 < 8; k8++) {
            uint32_t a0, a1, a2, a3;
            ldsm_x4(a0, a1, a2, a3, abase + k8 * 32);
            uint32_t bb = bbase + (uint32_t)(k8 * 16) * P3B;
            #pragma unroll
            for (int nb2 = 0; nb2 < 8; nb2++) {
                uint32_t b0, b1, b2, b3;
                ldsm_x4t(b0, b1, b2, b3, bb + nb2 * 32);
                mma16816(acc + nb2 * 8,     a0, a1, a2, a3, b0, b1);
                mma16816(acc + nb2 * 8 + 4, a0, a1, a2, a3, b2, b3);
            }
        }
    }
    __syncwarp();
    {
        int r0 = mbase + g, r1 = r0 + 8;
        #pragma unroll
        for (int nb = 0; nb < 16; nb++) {
            int c = (nb << 3) + (tg << 1);
            float v0 = silu_f(acc[nb*4+0] + sb1[c]);
            float v1 = silu_f(acc[nb*4+1] + sb1[c+1]);
            float v2 = silu_f(acc[nb*4+2] + sb1[c]);
            float v3 = silu_f(acc[nb*4+3] + sb1[c+1]);
            __nv_bfloat16 h0 = __float2bfloat16(v0), h1 = __float2bfloat16(v1);
            __nv_bfloat16 h2 = __float2bfloat16(v2), h3 = __float2bfloat16(v3);
            __nv_bfloat16 l0 = __float2bfloat16(v0 - __bfloat162float(h0));
            __nv_bfloat16 l1 = __float2bfloat16(v1 - __bfloat162float(h1));
            __nv_bfloat16 l2 = __float2bfloat16(v2 - __bfloat162float(h2));
            __nv_bfloat16 l3 = __float2bfloat16(v3 - __bfloat162float(h3));
            *(__nv_bfloat162*)(sm3 + OFF_XH + r0 * P3B + c * 2) = __halves2bfloat162(h0, h1);
            *(__nv_bfloat162*)(sm3 + OFF_XL + r0 * P3B + c * 2) = __halves2bfloat162(l0, l1);
            *(__nv_bfloat162*)(sm3 + OFF_XH + r1 * P3B + c * 2) = __halves2bfloat162(h2, h3);
            *(__nv_bfloat162*)(sm3 + OFF_XL + r1 * P3B + c * 2) = __halves2bfloat162(l2, l3);
        }
    }
    __syncwarp();

    #pragma unroll
    for (int i = 0; i < 64; i++) acc[i] = 0.f;
    #pragma unroll
    for (int pass = 0; pass < 3; pass++) {
        const int aoff = (pass == 2) ? OFF_XL  : OFF_XH;
        const int boff = (pass == 1) ? OFF_W2L : OFF_W2H;
        const uint32_t abase = sbu + aoff + (mbase + lrow) * P3B + lcol;
        const uint32_t bbase = sbu + boff + lrow * P3B + lcol;
        #pragma unroll
        for (int k8 = 0; k8 < 8; k8++) {
            uint32_t a0, a1, a2, a3;
            ldsm_x4(a0, a1, a2, a3, abase + k8 * 32);
            uint32_t bb = bbase + (uint32_t)(k8 * 16) * P3B;
            #pragma unroll
            for (int nb2 = 0; nb2 < 8; nb2++) {
                uint32_t b0, b1, b2, b3;
                ldsm_x4t(b0, b1, b2, b3, bb + nb2 * 32);
                mma16816(acc + nb2 * 8,     a0, a1, a2, a3, b0, b1);
                mma16816(acc + nb2 * 8 + 4, a0, a1, a2, a3, b2, b3);
            }
        }
    }
    {
        int n0 = nbase + mbase + g;
        int n1 = n0 + 8;
        #pragma unroll
        for (int nb = 0; nb < 16; nb++) {
            int c = (nb << 3) + (tg << 1);
            if (n0 < NNODES) {
                float2 hv = *(const float2*)(hin + n0 * HID + c);
                float2 o = make_float2(hv.x + acc[nb*4+0] + sb2[c],
                                       hv.y + acc[nb*4+1] + sb2[c+1]);
                *(float2*)(outp + n0 * HID + c) = o;
            }
            if (n1 < NNODES) {
                float2 hv = *(const float2*)(hin + n1 * HID + c);
                float2 o = make_float2(hv.x + acc[nb*4+2] + sb2[c],
                                       hv.y + acc[nb*4+3] + sb2[c+1]);
                *(float2*)(outp + n1 * HID + c) = o;
            }
        }
    }
}

extern "C" void kernel_launch(void* const* d_in, const int* in_sizes, int n_in,
                              void* d_out, int out_size)
{
    const float* h    = (const float*)d_in[0];
    const float* pos  = (const float*)d_in[1];
    const void*  ei   = d_in[2];
    const float* fw1  = (const float*)d_in[3];
    const float* fb1  = (const float*)d_in[4];
    const float* fw2  = (const float*)d_in[5];
    const float* fb2  = (const float*)d_in[6];
    const float* iw1  = (const float*)d_in[7];
    const float* ib1  = (const float*)d_in[8];
    const float* iw2  = (const float*)d_in[9];
    const float* ib2  = (const float*)d_in[10];
    float* out = (float*)d_out;

    cudaFuncSetAttribute(table_kernel, cudaFuncAttributeMaxDynamicSharedMemorySize, TBL_SMEM_BYTES);
    cudaFuncSetAttribute(node3_kernel, cudaFuncAttributeMaxDynamicSharedMemorySize, NODE3_SMEM);

    init_kernel<<<104, 512>>>(ei, iw1, iw2);
    scatter_kernel<<<GGRID, GNT>>>(pos, ei);
    table_kernel<<<NBINS / TROWS, NT, TBL_SMEM_BYTES>>>(fw1, fb1, fw2, fb2);
    htab_kernel<<<(NBINS * HID + 255) / 256, 256>>>();
    gather_kernel<<<GGRID, GNT>>>(h);
    node3_kernel<<<NODE3_GRID, 256, NODE3_SMEM>>>(h, out, ib1, ib2);
}

// round 13
// speedup vs baseline: 1.8002x; 1.0575x over previous
#include <cuda_runtime.h>
#include <cuda_fp16.h>
#include <cuda_bf16.h>
#include <cstdint>

#define NNODES  50000
#define NEDGES  640000
#define HID     128
#define NRBF    50
#define TILE    128
#define NT      512
#define CUTOFF_F 5.0f

#define NBINS   4096
#define TSTEP   (CUTOFF_F / (float)(NBINS - 1))
#define TINV    ((float)(NBINS - 1) / CUTOFF_F)

#define RBF_W   (CUTOFF_F / 49.0f)
#define RBF_IW  (49.0f / CUTOFF_F)

#define CAP     48

typedef unsigned long long ull;

__device__ float   g_agg[NNODES * HID];
__device__ float   g_table[NBINS * HID];
__device__ __half2 g_htab[NBINS * HID];
__device__ __align__(16) unsigned char g_wts[131072];
__device__ int     g_cnt[NNODES];
__device__ int2    g_rec[NNODES * CAP];
__device__ int g_is64;

// ---------- packed f32x2 helpers ----------
__device__ __forceinline__ void fma2(ull &acc, ull a, ull b) {
    asm("fma.rn.f32x2 %0, %1, %2, %0;" : "+l"(acc) : "l"(a), "l"(b));
}
__device__ __forceinline__ ull bcast2(float x) {
    ull r; asm("mov.b64 %0, {%1, %1};" : "=l"(r) : "f"(x)); return r;
}
__device__ __forceinline__ ull pack2(float x, float y) {
    ull r; asm("mov.b64 %0, {%1, %2};" : "=l"(r) : "f"(x), "f"(y)); return r;
}
__device__ __forceinline__ float2 unpack2(ull v) {
    float2 f; asm("mov.b64 {%0, %1}, %2;" : "=f"(f.x), "=f"(f.y) : "l"(v)); return f;
}
__device__ __forceinline__ float silu_f(float x) {
    return x / (1.0f + __expf(-x));
}

// ---------- mma helpers ----------
__device__ __forceinline__ uint32_t smem_u32(const void* p) {
    uint32_t a;
    asm("{ .reg .u64 t; cvta.to.shared.u64 t, %1; cvt.u32.u64 %0, t; }" : "=r"(a) : "l"(p));
    return a;
}
__device__ __forceinline__ void ldsm_x4(uint32_t &r0, uint32_t &r1, uint32_t &r2, uint32_t &r3, uint32_t a) {
    asm volatile("ldmatrix.sync.aligned.m8n8.x4.shared.b16 {%0,%1,%2,%3}, [%4];"
                 : "=r"(r0), "=r"(r1), "=r"(r2), "=r"(r3) : "r"(a));
}
__device__ __forceinline__ void ldsm_x4t(uint32_t &r0, uint32_t &r1, uint32_t &r2, uint32_t &r3, uint32_t a) {
    asm volatile("ldmatrix.sync.aligned.m8n8.x4.trans.shared.b16 {%0,%1,%2,%3}, [%4];"
                 : "=r"(r0), "=r"(r1), "=r"(r2), "=r"(r3) : "r"(a));
}
__device__ __forceinline__ void mma16816(float* d, uint32_t a0, uint32_t a1, uint32_t a2, uint32_t a3,
                                         uint32_t b0, uint32_t b1) {
    asm volatile("mma.sync.aligned.m16n8k16.row.col.f32.bf16.bf16.f32 "
                 "{%0,%1,%2,%3}, {%4,%5,%6,%7}, {%8,%9}, {%0,%1,%2,%3};"
                 : "+f"(d[0]), "+f"(d[1]), "+f"(d[2]), "+f"(d[3])
                 : "r"(a0), "r"(a1), "r"(a2), "r"(a3), "r"(b0), "r"(b1));
}

// ---------- merged init ----------
__global__ void init_kernel(const void* ei, const float* __restrict__ iw1,
                            const float* __restrict__ iw2) {
    int idx = blockIdx.x * blockDim.x + threadIdx.x;
    if (idx == 0) {
        const unsigned* u = (const unsigned*)ei;
        unsigned acc = 0;
        #pragma unroll
        for (int i = 0; i < 64; i++) acc |= u[2*i + 1];
        g_is64 = (acc == 0);
    }
    for (int i = idx; i < NNODES; i += gridDim.x * blockDim.x)
        g_cnt[i] = 0;
    if (idx < HID * HID) {
        float v1 = iw1[idx];
        __nv_bfloat16 h1 = __float2bfloat16(v1);
        __nv_bfloat16 l1 = __float2bfloat16(v1 - __bfloat162float(h1));
        *(__nv_bfloat16*)(g_wts + 0     + idx*2) = h1;
        *(__nv_bfloat16*)(g_wts + 32768 + idx*2) = l1;
        float v2 = iw2[idx];
        __nv_bfloat16 h2 = __float2bfloat16(v2);
        __nv_bfloat16 l2 = __float2bfloat16(v2 - __bfloat162float(h2));
        *(__nv_bfloat16*)(g_wts + 65536 + idx*2) = h2;
        *(__nv_bfloat16*)(g_wts + 98304 + idx*2) = l2;
    }
}

// ---------- scatter ----------
#define GNT 256
#define GGRID 1184

__global__ __launch_bounds__(GNT)
void scatter_kernel(const float* __restrict__ pos, const void* __restrict__ ei) {
    const int is64 = g_is64;
    for (int g = blockIdx.x * blockDim.x + threadIdx.x; g < NEDGES; g += gridDim.x * blockDim.x) {
        int r, c;
        if (is64) {
            r = (int)__ldg((const long long*)ei + g);
            c = (int)__ldg((const long long*)ei + NEDGES + g);
        } else {
            r = __ldg((const int*)ei + g);
            c = __ldg((const int*)ei + NEDGES + g);
        }
        float dx = pos[r*3+0] - pos[c*3+0];
        float dy = pos[r*3+1] - pos[c*3+1];
        float dz = pos[r*3+2] - pos[c*3+2];
        float d  = sqrtf(dx*dx + dy*dy + dz*dz + 1e-8f);
        if (d > CUTOFF_F) continue;
        float t = d * TINV;
        if (t > (float)(NBINS - 1)) t = (float)(NBINS - 1);
        int slot = atomicAdd(&g_cnt[r], 1);
        if (slot < CAP)
            g_rec[r * CAP + slot] = make_int2(c, __float_as_int(t));
    }
}

// ---------- table build kernel (R12, 32 rows/CTA) ----------
#define TROWS 32
#define S1P   132
#define TBL_SMEM_FLOATS (NRBF*HID + HID*HID + TROWS*NRBF + TROWS*S1P + TROWS)
#define TBL_SMEM_BYTES  (TBL_SMEM_FLOATS * 4)

__global__ __launch_bounds__(NT, 1)
void table_kernel(const float* __restrict__ fw1, const float* __restrict__ fb1,
                  const float* __restrict__ fw2, const float* __restrict__ fb2)
{
    extern __shared__ float sm[];
    float* fw1_s  = sm;
    float* fw2_s  = fw1_s + NRBF * HID;
    float* rbf_s  = fw2_s + HID * HID;
    float* s1_s   = rbf_s + TROWS * NRBF;
    float* cut_s  = s1_s + TROWS * S1P;

    const int tid = threadIdx.x;
    const int rbase = blockIdx.x * TROWS;
    const int row = tid >> 4;
    const int c0  = (tid & 15) * 8;

    {
        const float4* w1 = (const float4*)fw1; float4* d1 = (float4*)fw1_s;
        for (int i = tid; i < NRBF*HID/4; i += NT) d1[i] = w1[i];
        const float4* w2 = (const float4*)fw2; float4* d2 = (float4*)fw2_s;
        for (int i = tid; i < HID*HID/4; i += NT) d2[i] = w2[i];
    }
    if (tid < TROWS) {
        float d = (float)(rbase + tid) * TSTEP;
        cut_s[tid] = 0.5f * (__cosf(d * (3.14159265358979323846f / CUTOFF_F)) + 1.0f);
    }
    for (int idx = tid; idx < TROWS * NRBF; idx += NT) {
        int e = idx / NRBF;
        int k = idx - e * NRBF;
        float d = (float)(rbase + e) * TSTEP;
        float t = (d - (float)k * RBF_W) * RBF_IW;
        rbf_s[idx] = __expf(-0.5f * t * t);
    }
    __syncthreads();

    ull acc[4];
    {
        float4 ba = *(const float4*)(fb1 + c0);
        float4 bb = *(const float4*)(fb1 + c0 + 4);
        acc[0] = pack2(ba.x, ba.y); acc[1] = pack2(ba.z, ba.w);
        acc[2] = pack2(bb.x, bb.y); acc[3] = pack2(bb.z, bb.w);
    }
    {
        const float* rb = rbf_s + row * NRBF;
        #pragma unroll 5
        for (int k = 0; k < NRBF; k++) {
            ull a = bcast2(rb[k]);
            const ulonglong2* wp = (const ulonglong2*)(fw1_s + k*HID + c0);
            ulonglong2 w01 = wp[0], w23 = wp[1];
            fma2(acc[0], a, w01.x); fma2(acc[1], a, w01.y);
            fma2(acc[2], a, w23.x); fma2(acc[3], a, w23.y);
        }
    }
    {
        float4 o0, o1; float2 v;
        v = unpack2(acc[0]); o0.x = silu_f(v.x); o0.y = silu_f(v.y);
        v = unpack2(acc[1]); o0.z = silu_f(v.x); o0.w = silu_f(v.y);
        v = unpack2(acc[2]); o1.x = silu_f(v.x); o1.y = silu_f(v.y);
        v = unpack2(acc[3]); o1.z = silu_f(v.x); o1.w = silu_f(v.y);
        *(float4*)(s1_s + row*S1P + c0)     = o0;
        *(float4*)(s1_s + row*S1P + c0 + 4) = o1;
    }
    __syncthreads();

    {
        float4 ba = *(const float4*)(fb2 + c0);
        float4 bb = *(const float4*)(fb2 + c0 + 4);
        acc[0] = pack2(ba.x, ba.y); acc[1] = pack2(ba.z, ba.w);
        acc[2] = pack2(bb.x, bb.y); acc[3] = pack2(bb.z, bb.w);
    }
    {
        const float* sb = s1_s + row * S1P;
        #pragma unroll 4
        for (int k = 0; k < HID; k++) {
            ull a = bcast2(sb[k]);
            const ulonglong2* wp = (const ulonglong2*)(fw2_s + k*HID + c0);
            ulonglong2 w01 = wp[0], w23 = wp[1];
            fma2(acc[0], a, w01.x); fma2(acc[1], a, w01.y);
            fma2(acc[2], a, w23.x); fma2(acc[3], a, w23.y);
        }
    }
    {
        int r = rbase + row;
        float ct = cut_s[row];
        float2 v0 = unpack2(acc[0]);
        float2 v1 = unpack2(acc[1]);
        float2 v2 = unpack2(acc[2]);
        float2 v3 = unpack2(acc[3]);
        float4 o0 = make_float4(v0.x*ct, v0.y*ct, v1.x*ct, v1.y*ct);
        float4 o1 = make_float4(v2.x*ct, v2.y*ct, v3.x*ct, v3.y*ct);
        *(float4*)(g_table + r*HID + c0)     = o0;
        *(float4*)(g_table + r*HID + c0 + 4) = o1;
    }
}

// ---------- fp16 {value, slope} table ----------
__global__ void htab_kernel() {
    int idx = blockIdx.x * blockDim.x + threadIdx.x;
    const int n = NBINS * HID;
    if (idx >= n) return;
    float v = g_table[idx];
    float s = (idx + HID < n) ? (g_table[idx + HID] - v) : 0.f;
    g_htab[idx] = __floats2half2_rn(v, s);
}

// ---------- CSR gather (unchanged) ----------
__global__ __launch_bounds__(GNT)
void gather_kernel(const float* __restrict__ hin)
{
    const int lane = threadIdx.x & 31;
    const int c0 = lane * 4;
    int n = (blockIdx.x * GNT + threadIdx.x) >> 5;
    const int nstride = (GGRID * GNT) >> 5;

    for (; n < NNODES; n += nstride) {
        int cnt = __ldg(&g_cnt[n]);
        if (cnt > CAP) cnt = CAP;
        const int2* recs = g_rec + n * CAP;
        float4 acc = make_float4(0.f, 0.f, 0.f, 0.f);

        #pragma unroll 2
        for (int e = 0; e < cnt; e++) {
            int2 rec = __ldg(&recs[e]);
            float t = __int_as_float(rec.y);
            int i0 = (int)t;
            float fr = t - (float)i0;

            uint4 q = *(const uint4*)(g_htab + i0*HID + c0);
            float4 hv = __ldg((const float4*)(hin + rec.x*HID + c0));

            float2 t0 = __half22float2(*(__half2*)&q.x);
            float2 t1 = __half22float2(*(__half2*)&q.y);
            float2 t2 = __half22float2(*(__half2*)&q.z);
            float2 t3 = __half22float2(*(__half2*)&q.w);

            acc.x = fmaf(hv.x, fmaf(fr, t0.y, t0.x), acc.x);
            acc.y = fmaf(hv.y, fmaf(fr, t1.y, t1.x), acc.y);
            acc.z = fmaf(hv.z, fmaf(fr, t2.y, t2.x), acc.z);
            acc.w = fmaf(hv.w, fmaf(fr, t3.y, t3.x), acc.w);
        }
        *(float4*)(g_agg + n*HID + c0) = acc;
    }
}

// ---------- node kernel: mma.sync bf16 3-way split, m64 x n32 warp tiles ----------
#define P3      136
#define P3B     (P3 * 2)
#define T3B     (128 * P3B)
#define OFF_XH  0
#define OFF_XL  (T3B)
#define OFF_W1H (2 * T3B)
#define OFF_W1L (3 * T3B)
#define OFF_W2H (4 * T3B)
#define OFF_W2L (5 * T3B)
#define OFF_SB1 (6 * T3B)
#define OFF_SB2 (6 * T3B + 512)
#define NODE3_SMEM (6 * T3B + 1024)
#define NODE3_GRID ((NNODES + TILE - 1) / TILE)

__global__ void __launch_bounds__(256, 1)
node3_kernel(const float* __restrict__ hin, float* __restrict__ outp,
             const float* __restrict__ ib1, const float* __restrict__ ib2)
{
    extern __shared__ unsigned char sm3[];
    const uint32_t sbu = smem_u32(sm3);
    float* sb1 = (float*)(sm3 + OFF_SB1);
    float* sb2 = (float*)(sm3 + OFF_SB2);

    const int tid  = threadIdx.x;
    const int wid  = tid >> 5;
    const int lane = tid & 31;
    const int nbase = blockIdx.x * TILE;

    // stage weights
    {
        const int WOFF[4] = {OFF_W1H, OFF_W1L, OFF_W2H, OFF_W2L};
        for (int i = tid; i < 4 * 128 * 16; i += 256) {
            int t   = i >> 11;
            int rem = i & 2047;
            int row = rem >> 4;
            int q   = rem & 15;
            uint4 v = *(const uint4*)(g_wts + t * 32768 + row * 256 + q * 16);
            *(uint4*)(sm3 + WOFF[t] + row * P3B + q * 16) = v;
        }
    }
    if (tid < 128) { sb1[tid] = ib1[tid]; sb2[tid] = ib2[tid]; }

    // stage x (hi/lo split)
    for (int idx = tid; idx < 128 * 32; idx += 256) {
        int n  = idx >> 5;
        int c4 = (idx & 31) << 2;
        float4 v = make_float4(0.f, 0.f, 0.f, 0.f);
        if (nbase + n < NNODES) v = __ldg((const float4*)(g_agg + (nbase + n) * HID + c4));
        __nv_bfloat16 hx = __float2bfloat16(v.x), hy = __float2bfloat16(v.y);
        __nv_bfloat16 hz = __float2bfloat16(v.z), hw = __float2bfloat16(v.w);
        __nv_bfloat16 lx = __float2bfloat16(v.x - __bfloat162float(hx));
        __nv_bfloat16 ly = __float2bfloat16(v.y - __bfloat162float(hy));
        __nv_bfloat16 lz = __float2bfloat16(v.z - __bfloat162float(hz));
        __nv_bfloat16 lw = __float2bfloat16(v.w - __bfloat162float(hw));
        int o = n * P3B + c4 * 2;
        *(__nv_bfloat162*)(sm3 + OFF_XH + o)     = __halves2bfloat162(hx, hy);
        *(__nv_bfloat162*)(sm3 + OFF_XH + o + 4) = __halves2bfloat162(hz, hw);
        *(__nv_bfloat162*)(sm3 + OFF_XL + o)     = __halves2bfloat162(lx, ly);
        *(__nv_bfloat162*)(sm3 + OFF_XL + o + 4) = __halves2bfloat162(lz, lw);
    }
    __syncthreads();

    // warp tiling: 2 m-groups x 4 n-groups; warp tile = m64 x n32
    const int mg = wid >> 2;              // 0..1
    const int ng = wid & 3;               // 0..3
    const int mbase = mg * 64;
    const int cbase = ng * 32;
    const int g  = lane >> 2;
    const int tg = lane & 3;
    const uint32_t lrow = (lane & 15);
    const uint32_t lcol = ((lane >> 4) & 1) << 4;

    // acc[i*16 + nb*4 + q]: m-frag i (m16), n8-block nb, quad element q
    float acc[64];

    // ================= GEMM1 =================
    #pragma unroll
    for (int i = 0; i < 64; i++) acc[i] = 0.f;
    #pragma unroll
    for (int pass = 0; pass < 3; pass++) {
        const int aoff = (pass == 2) ? OFF_XL  : OFF_XH;
        const int boff = (pass == 1) ? OFF_W1L : OFF_W1H;
        const uint32_t abase = sbu + aoff + (mbase + lrow) * P3B + lcol;
        const uint32_t bbase = sbu + boff + lrow * P3B + lcol + cbase * 2;
        #pragma unroll
        for (int k8 = 0; k8 < 8; k8++) {
            uint32_t a[4][4];
            #pragma unroll
            for (int i = 0; i < 4; i++)
                ldsm_x4(a[i][0], a[i][1], a[i][2], a[i][3],
                        abase + (uint32_t)(i * 16) * P3B + k8 * 32);
            uint32_t b[2][4];
            #pragma unroll
            for (int j = 0; j < 2; j++)
                ldsm_x4t(b[j][0], b[j][1], b[j][2], b[j][3],
                         bbase + (uint32_t)(k8 * 16) * P3B + j * 32);
            #pragma unroll
            for (int i = 0; i < 4; i++) {
                mma16816(acc + i*16 + 0,  a[i][0], a[i][1], a[i][2], a[i][3], b[0][0], b[0][1]);
                mma16816(acc + i*16 + 4,  a[i][0], a[i][1], a[i][2], a[i][3], b[0][2], b[0][3]);
                mma16816(acc + i*16 + 8,  a[i][0], a[i][1], a[i][2], a[i][3], b[1][0], b[1][1]);
                mma16816(acc + i*16 + 12, a[i][0], a[i][1], a[i][2], a[i][3], b[1][2], b[1][3]);
            }
        }
    }
    __syncthreads();   // all GEMM1 reads of xh/xl done before overwrite

    // epilogue 1: bias + silu + hi/lo split back (own m64 x n32 region)
    #pragma unroll
    for (int i = 0; i < 4; i++) {
        int r0 = mbase + i*16 + g, r1 = r0 + 8;
        #pragma unroll
        for (int nb = 0; nb < 4; nb++) {
            int c = cbase + nb*8 + tg*2;
            float v0 = silu_f(acc[i*16+nb*4+0] + sb1[c]);
            float v1 = silu_f(acc[i*16+nb*4+1] + sb1[c+1]);
            float v2 = silu_f(acc[i*16+nb*4+2] + sb1[c]);
            float v3 = silu_f(acc[i*16+nb*4+3] + sb1[c+1]);
            __nv_bfloat16 h0 = __float2bfloat16(v0), h1 = __float2bfloat16(v1);
            __nv_bfloat16 h2 = __float2bfloat16(v2), h3 = __float2bfloat16(v3);
            __nv_bfloat16 l0 = __float2bfloat16(v0 - __bfloat162float(h0));
            __nv_bfloat16 l1 = __float2bfloat16(v1 - __bfloat162float(h1));
            __nv_bfloat16 l2 = __float2bfloat16(v2 - __bfloat162float(h2));
            __nv_bfloat16 l3 = __float2bfloat16(v3 - __bfloat162float(h3));
            *(__nv_bfloat162*)(sm3 + OFF_XH + r0 * P3B + c * 2) = __halves2bfloat162(h0, h1);
            *(__nv_bfloat162*)(sm3 + OFF_XL + r0 * P3B + c * 2) = __halves2bfloat162(l0, l1);
            *(__nv_bfloat162*)(sm3 + OFF_XH + r1 * P3B + c * 2) = __halves2bfloat162(h2, h3);
            *(__nv_bfloat162*)(sm3 + OFF_XL + r1 * P3B + c * 2) = __halves2bfloat162(l2, l3);
        }
    }
    __syncthreads();   // s1 fully written (cross-warp dependency in GEMM2)

    // ================= GEMM2 =================
    #pragma unroll
    for (int i = 0; i < 64; i++) acc[i] = 0.f;
    #pragma unroll
    for (int pass = 0; pass < 3; pass++) {
        const int aoff = (pass == 2) ? OFF_XL  : OFF_XH;
        const int boff = (pass == 1) ? OFF_W2L : OFF_W2H;
        const uint32_t abase = sbu + aoff + (mbase + lrow) * P3B + lcol;
        const uint32_t bbase = sbu + boff + lrow * P3B + lcol + cbase * 2;
        #pragma unroll
        for (int k8 = 0; k8 < 8; k8++) {
            uint32_t a[4][4];
            #pragma unroll
            for (int i = 0; i < 4; i++)
                ldsm_x4(a[i][0], a[i][1], a[i][2], a[i][3],
                        abase + (uint32_t)(i * 16) * P3B + k8 * 32);
            uint32_t b[2][4];
            #pragma unroll
            for (int j = 0; j < 2; j++)
                ldsm_x4t(b[j][0], b[j][1], b[j][2], b[j][3],
                         bbase + (uint32_t)(k8 * 16) * P3B + j * 32);
            #pragma unroll
            for (int i = 0; i < 4; i++) {
                mma16816(acc + i*16 + 0,  a[i][0], a[i][1], a[i][2], a[i][3], b[0][0], b[0][1]);
                mma16816(acc + i*16 + 4,  a[i][0], a[i][1], a[i][2], a[i][3], b[0][2], b[0][3]);
                mma16816(acc + i*16 + 8,  a[i][0], a[i][1], a[i][2], a[i][3], b[1][0], b[1][1]);
                mma16816(acc + i*16 + 12, a[i][0], a[i][1], a[i][2], a[i][3], b[1][2], b[1][3]);
            }
        }
    }

    // epilogue 2: out = h + (D2 + b2)
    #pragma unroll
    for (int i = 0; i < 4; i++) {
        int n0 = nbase + mbase + i*16 + g;
        int n1 = n0 + 8;
        #pragma unroll
        for (int nb = 0; nb < 4; nb++) {
            int c = cbase + nb*8 + tg*2;
            if (n0 < NNODES) {
                float2 hv = *(const float2*)(hin + n0 * HID + c);
                float2 o = make_float2(hv.x + acc[i*16+nb*4+0] + sb2[c],
                                       hv.y + acc[i*16+nb*4+1] + sb2[c+1]);
                *(float2*)(outp + n0 * HID + c) = o;
            }
            if (n1 < NNODES) {
                float2 hv = *(const float2*)(hin + n1 * HID + c);
                float2 o = make_float2(hv.x + acc[i*16+nb*4+2] + sb2[c],
                                       hv.y + acc[i*16+nb*4+3] + sb2[c+1]);
                *(float2*)(outp + n1 * HID + c) = o;
            }
        }
    }
}

extern "C" void kernel_launch(void* const* d_in, const int* in_sizes, int n_in,
                              void* d_out, int out_size)
{
    const float* h    = (const float*)d_in[0];
    const float* pos  = (const float*)d_in[1];
    const void*  ei   = d_in[2];
    const float* fw1  = (const float*)d_in[3];
    const float* fb1  = (const float*)d_in[4];
    const float* fw2  = (const float*)d_in[5];
    const float* fb2  = (const float*)d_in[6];
    const float* iw1  = (const float*)d_in[7];
    const float* ib1  = (const float*)d_in[8];
    const float* iw2  = (const float*)d_in[9];
    const float* ib2  = (const float*)d_in[10];
    float* out = (float*)d_out;

    cudaFuncSetAttribute(table_kernel, cudaFuncAttributeMaxDynamicSharedMemorySize, TBL_SMEM_BYTES);
    cudaFuncSetAttribute(node3_kernel, cudaFuncAttributeMaxDynamicSharedMemorySize, NODE3_SMEM);

    init_kernel<<<104, 512>>>(ei, iw1, iw2);
    scatter_kernel<<<GGRID, GNT>>>(pos, ei);
    table_kernel<<<NBINS / TROWS, NT, TBL_SMEM_BYTES>>>(fw1, fb1, fw2, fb2);
    htab_kernel<<<(NBINS * HID + 255) / 256, 256>>>();
    gather_kernel<<<GGRID, GNT>>>(h);
    node3_kernel<<<NODE3_GRID, 256, NODE3_SMEM>>>(h, out, ib1, ib2);
}